// round 12
// baseline (speedup 1.0000x reference)
#include <cuda_runtime.h>
#include <cuda_fp16.h>
#include <cstdint>
#include <math.h>

typedef unsigned int u32;

#define BDIM 2
#define LDIM 2048
#define EDIM 1024
#define HDIM 16
#define DDIM 64
#define MDIM (BDIM * LDIM)   // 4096
#define WSZ (EDIM * EDIM)

// ---------------- scratch (device globals; allocation is forbidden) --------
__device__ __half g_q[BDIM * HDIM * LDIM * DDIM];   // [B,H,L,D]
__device__ __half g_k[BDIM * HDIM * LDIM * DDIM];
__device__ __half g_v[BDIM * HDIM * LDIM * DDIM];
__device__ __half g_hs[MDIM * EDIM];
__device__ __half g_ctx[MDIM * EDIM];               // [B,L,E]
__device__ __half g_w[4 * EDIM * EDIM];             // Wq,Wk,Wv,Wo
__device__ float g_meanv[BDIM * HDIM * DDIM];       // [B,H,D]

// ---------------------------------------------------------------------------
// helpers
// ---------------------------------------------------------------------------
__device__ __forceinline__ u32 packh(float lo, float hi) {
    u32 d;
    asm("cvt.rn.f16x2.f32 %0, %1, %2;" : "=r"(d) : "f"(hi), "f"(lo));
    return d;
}

__device__ __forceinline__ void cpasync16(u32 dst, const void* src) {
    asm volatile("cp.async.cg.shared.global [%0], [%1], 16;\n" :: "r"(dst), "l"(src));
}
__device__ __forceinline__ void cp_commit() { asm volatile("cp.async.commit_group;\n"); }
__device__ __forceinline__ void cp_wait1() { asm volatile("cp.async.wait_group 1;\n"); }
__device__ __forceinline__ void cp_wait0() { asm volatile("cp.async.wait_group 0;\n"); }

__device__ __forceinline__ void ldsm4(u32& r0, u32& r1, u32& r2, u32& r3, u32 addr) {
    asm volatile("ldmatrix.sync.aligned.m8n8.x4.shared.b16 {%0,%1,%2,%3}, [%4];"
        : "=r"(r0), "=r"(r1), "=r"(r2), "=r"(r3) : "r"(addr));
}
__device__ __forceinline__ void ldsm4t(u32& r0, u32& r1, u32& r2, u32& r3, u32 addr) {
    asm volatile("ldmatrix.sync.aligned.m8n8.x4.trans.shared.b16 {%0,%1,%2,%3}, [%4];"
        : "=r"(r0), "=r"(r1), "=r"(r2), "=r"(r3) : "r"(addr));
}
__device__ __forceinline__ void mma16816(float* acc, const u32* a, const u32* b) {
    asm volatile("mma.sync.aligned.m16n8k16.row.col.f32.f16.f16.f32 "
        "{%0,%1,%2,%3}, {%4,%5,%6,%7}, {%8,%9}, {%0,%1,%2,%3};"
        : "+f"(acc[0]), "+f"(acc[1]), "+f"(acc[2]), "+f"(acc[3])
        : "r"(a[0]), "r"(a[1]), "r"(a[2]), "r"(a[3]), "r"(b[0]), "r"(b[1]));
}

// ---------------------------------------------------------------------------
// Fused fp32 -> fp16 convert for hidden_states + all 4 weight matrices
// ---------------------------------------------------------------------------
#define HS4 (MDIM * EDIM / 4)
#define W4 (WSZ / 4)

__global__ __launch_bounds__(256)
void conv_all(const float* __restrict__ hs,
              const float* __restrict__ w0, const float* __restrict__ w1,
              const float* __restrict__ w2, const float* __restrict__ w3,
              __half* __restrict__ ohs, __half* __restrict__ ow)
{
    int i = blockIdx.x * blockDim.x + threadIdx.x;
    const float* src;
    uint2* dst;
    int j;
    if (i < HS4) {
        src = hs; j = i; dst = (uint2*)ohs + i;
    } else {
        const int t = i - HS4;
        const int m = t / W4;
        j = t - m * W4;
        src = (m == 0) ? w0 : (m == 1) ? w1 : (m == 2) ? w2 : w3;
        dst = (uint2*)ow + t;
    }
    float4 v = ((const float4*)src)[j];
    uint2 hv;
    hv.x = packh(v.x, v.y);
    hv.y = packh(v.z, v.w);
    *dst = hv;
}

// ---------------------------------------------------------------------------
// mean(V): single-kernel deterministic reduction. grid=32, block=1024.
// 16 threads per d-column, 128 rows each; smem tree reduce.
// ---------------------------------------------------------------------------
__global__ __launch_bounds__(1024)
void meanv_kernel(float* __restrict__ mv)
{
    __shared__ float red[1024];
    const int bh = blockIdx.x;
    const int tid = threadIdx.x;
    const int d = tid & 63;
    const int sub = tid >> 6;             // 0..15
    const __half* vb = g_v + (size_t)bh * LDIM * DDIM;
    const int l0 = sub * 128;
    float s = 0.f;
#pragma unroll 4
    for (int l = l0; l < l0 + 128; l++)
        s += __half2float(vb[(size_t)l * DDIM + d]);
    red[tid] = s;
    __syncthreads();
    if (tid < 64) {
        float t = 0.f;
#pragma unroll
        for (int k = 0; k < 16; k++)
            t += red[d + 64 * k];
        mv[bh * DDIM + d] = t * (1.0f / 2048.0f);
    }
}

// ---------------------------------------------------------------------------
// fp16 tensor-core NT GEMM, fused-QKV capable (round-10 validated).
// Tile 128(M) x 256(N), BK=64, 3-stage cp.async, 512 thr / 16 warps (4Mx4N).
// ---------------------------------------------------------------------------
#define SSTR 72                           // smem row stride in fp16 (144 B)
#define A_ARR (128 * SSTR * 2)            // 18432 B
#define B_ARR (256 * SSTR * 2)            // 36864 B
#define O_A 0
#define O_B A_ARR
#define STG (A_ARR + B_ARR)               // 55296 B
#define G_SMEM (3 * STG)                  // 165888 B

__device__ __forceinline__ void g_issue(
    u32 sbase, int s, int k0, int tid,
    const __half* A, const __half* B, int bm, int bn)
{
    const u32 st = sbase + (u32)(s % 3) * STG;
#pragma unroll
    for (int i = 0; i < 2; i++) {
        const int c = tid + i * 512;
        const int row = c >> 3, ch = c & 7;
        const u32 so = (u32)(row * (SSTR * 2) + ch * 16);
        cpasync16(st + O_A + so, A + (size_t)(bm + row) * EDIM + k0 + ch * 8);
    }
#pragma unroll
    for (int i = 0; i < 4; i++) {
        const int c = tid + i * 512;
        const int row = c >> 3, ch = c & 7;
        const u32 so = (u32)(row * (SSTR * 2) + ch * 16);
        cpasync16(st + O_B + so, B + (size_t)(bn + row) * EDIM + k0 + ch * 8);
    }
    cp_commit();
}

extern "C" __global__ __launch_bounds__(512, 1)
void gemm_h(const __half* __restrict__ Ag, const __half* __restrict__ Wbase,
            const float* __restrict__ b0, const float* __restrict__ b2,
            float* __restrict__ out,
            u32* __restrict__ o0, u32* __restrict__ o1, u32* __restrict__ o2,
            int fused)
{
    extern __shared__ __align__(16) char dynsmem[];
    const u32 sbase = (u32)__cvta_generic_to_shared(dynsmem);
    const int bm = blockIdx.y * 128;
    const int bn = blockIdx.x * 256;
    const int z = blockIdx.z;
    const int tid = threadIdx.x;
    const int lane = tid & 31;
    const int wid = tid >> 5;
    const int wm = (wid & 3) * 32;
    const int wn = (wid >> 2) * 64;

    const __half* Bg = Wbase + (size_t)z * WSZ;
    const float* bias;
    float alpha;
    u32* outq;
    if (fused) {
        bias = (z == 0) ? b0 : ((z == 2) ? b2 : nullptr);
        alpha = (z == 0) ? 0.125f : 1.0f;
        outq = (z == 0) ? o0 : ((z == 1) ? o1 : o2);
    } else {
        bias = b0; alpha = 1.0f; outq = nullptr;
    }

    float acc[2][8][4];
#pragma unroll
    for (int i = 0; i < 2; i++)
#pragma unroll
        for (int j = 0; j < 8; j++)
#pragma unroll
            for (int c = 0; c < 4; c++) acc[i][j][c] = 0.f;

    const int lrA = wm + (lane & 15);
    const int lrB = wn + (lane & 15);
    const int lcol = (lane >> 4) * 8;

    const int NIT = EDIM / 64;            // 16
    g_issue(sbase, 0, 0, tid, Ag, Bg, bm, bn);
    g_issue(sbase, 1, 64, tid, Ag, Bg, bm, bn);

    for (int it = 0; it < NIT; it++) {
        if (it + 1 < NIT) cp_wait1(); else cp_wait0();
        __syncthreads();
        if (it + 2 < NIT)
            g_issue(sbase, it + 2, (it + 2) * 64, tid, Ag, Bg, bm, bn);

        const u32 st = sbase + (u32)(it % 3) * STG;
#pragma unroll
        for (int ks = 0; ks < 4; ks++) {
            const int kb = ks * 16;
            u32 ah[2][4];
#pragma unroll
            for (int mt = 0; mt < 2; mt++) {
                const u32 ad = st + O_A + (u32)((lrA + mt * 16) * SSTR + kb + lcol) * 2;
                ldsm4(ah[mt][0], ah[mt][1], ah[mt][2], ah[mt][3], ad);
            }
#pragma unroll
            for (int p = 0; p < 4; p++) {
                const u32 bd = st + O_B + (u32)((lrB + p * 16) * SSTR + kb + lcol) * 2;
                u32 t0, t1, t2, t3;
                u32 b0r[2], b1r[2];
                ldsm4(t0, t1, t2, t3, bd);
                b0r[0] = t0; b0r[1] = t2; b1r[0] = t1; b1r[1] = t3;
#pragma unroll
                for (int mt = 0; mt < 2; mt++) {
                    mma16816(acc[mt][2 * p], ah[mt], b0r);
                    mma16816(acc[mt][2 * p + 1], ah[mt], b1r);
                }
            }
        }
        __syncthreads();
    }

    // ----- epilogue -----
#pragma unroll
    for (int mt = 0; mt < 2; mt++) {
#pragma unroll
        for (int nt = 0; nt < 8; nt++) {
#pragma unroll
            for (int r = 0; r < 2; r++) {
                const int row = bm + wm + mt * 16 + (lane >> 2) + r * 8;
                const int col0 = bn + wn + nt * 8 + (lane & 3) * 2;
                float v0 = acc[mt][nt][r * 2 + 0];
                float v1 = acc[mt][nt][r * 2 + 1];
                if (bias) { v0 += bias[col0]; v1 += bias[col0 + 1]; }
                v0 *= alpha; v1 *= alpha;
                const int b = row >> 11;
                const int l = row & (LDIM - 1);
                if (fused) {
                    const int h = col0 >> 6;
                    const int d = col0 & (DDIM - 1);
                    const size_t e = (((size_t)(b * HDIM + h) * LDIM) + l) * DDIM + d;
                    outq[e >> 1] = packh(v0, v1);
                } else {
                    out[(size_t)row * EDIM + col0] = v0;
                    out[(size_t)row * EDIM + col0 + 1] = v1;
                }
            }
        }
    }
}

// ---------------------------------------------------------------------------
// fp16 tensor-core flash attention; handles invalid rows inline (writes
// mean(V) for q >= seq_len, replacing the old fill_invalid kernel).
// ---------------------------------------------------------------------------
#define STR 72
#define Q_OFF 0
#define ST_BASE (128 * STR * 2)           // 18432
#define KT_B (64 * STR * 2)               // 9216
#define K_O 0
#define V_O KT_B
#define ST_SZ (2 * KT_B)                  // 18432
#define ATT_SMEM (ST_BASE + 2 * ST_SZ)    // 55296

__device__ __forceinline__ void attn_issue_kv(u32 base, int kbase, int tid,
                                              const __half* kg, const __half* vg)
{
    const int row = tid >> 1;
    const int c0 = (tid & 1) * 4;
#pragma unroll
    for (int c = 0; c < 4; c++) {
        const int ch = c0 + c;
        const u32 off = (u32)((row * STR + ch * 8) * 2);
        const size_t src = (size_t)(kbase + row) * DDIM + ch * 8;
        cpasync16(base + K_O + off, kg + src);
        cpasync16(base + V_O + off, vg + src);
    }
}

__global__ __launch_bounds__(128)
void attn_mma(const int* __restrict__ seq_len, const float* __restrict__ mv,
              u32* __restrict__ ctx)
{
    extern __shared__ __align__(16) char sm[];
    const u32 sb = (u32)__cvta_generic_to_shared(sm);
    const int bh = blockIdx.y;
    const int b = bh >> 4;
    const int h = bh & (HDIM - 1);
    const int qt = (int)gridDim.x - 1 - (int)blockIdx.x;
    const int q0 = qt * 128;
    const int sl = seq_len[b];
    const int tid = threadIdx.x;

    if (q0 >= sl) {
        // fully invalid block: write mean(V) rows to ctx and exit
        const int cp = tid & 31;          // column pair within head (0..31)
        const int r0 = tid >> 5;          // 0..3
        const u32 mval = packh(mv[b * 1024 + h * 64 + cp * 2],
                               mv[b * 1024 + h * 64 + cp * 2 + 1]);
        for (int r = r0; r < 128; r += 4) {
            const size_t e = (size_t)(b * LDIM + q0 + r) * 512 + h * 32 + cp;
            ctx[e] = mval;
        }
        return;
    }

    const int lane = tid & 31;
    const int w = tid >> 5;
    const int wm = w * 32;
    const int g = lane >> 2;
    const int qd = lane & 3;

    const size_t hoff = (size_t)bh * LDIM * DDIM;
    const __half* qg = g_q + hoff;
    const __half* kg = g_k + hoff;
    const __half* vg = g_v + hoff;

    {
        const int row = tid;
        const size_t src = (size_t)(q0 + row) * DDIM;
#pragma unroll
        for (int c = 0; c < 8; c++)
            cpasync16(sb + Q_OFF + (u32)((row * STR + c * 8) * 2), qg + src + c * 8);
    }
    attn_issue_kv(sb + ST_BASE, 0, tid, kg, vg);
    cp_commit();

    const int qend = min(q0 + 127, sl - 1);
    const int ntiles = (qend >> 6) + 1;

    float o[2][8][4];
    float mrow[4], lrow[4];
#pragma unroll
    for (int i = 0; i < 2; i++)
#pragma unroll
        for (int j = 0; j < 8; j++)
#pragma unroll
            for (int c = 0; c < 4; c++) o[i][j][c] = 0.f;
#pragma unroll
    for (int i = 0; i < 4; i++) { mrow[i] = -1e30f; lrow[i] = 0.f; }

    for (int t = 0; t < ntiles; t++) {
        if (t + 1 < ntiles) {
            attn_issue_kv(sb + ST_BASE + (u32)((t + 1) & 1) * ST_SZ, (t + 1) << 6,
                          tid, kg, vg);
            cp_commit();
            cp_wait1();
        } else {
            cp_wait0();
        }
        __syncthreads();

        const u32 kb_ = sb + ST_BASE + (u32)(t & 1) * ST_SZ;

        float s[2][8][4];
#pragma unroll
        for (int i = 0; i < 2; i++)
#pragma unroll
            for (int j = 0; j < 8; j++)
#pragma unroll
                for (int c = 0; c < 4; c++) s[i][j][c] = 0.f;

#pragma unroll
        for (int kf = 0; kf < 4; kf++) {
            u32 aq[2][4];
#pragma unroll
            for (int mf = 0; mf < 2; mf++) {
                const u32 ad = sb + Q_OFF + (u32)(((wm + mf * 16 + (lane & 15)) * STR
                                      + kf * 16 + (lane >> 4) * 8) * 2);
                ldsm4(aq[mf][0], aq[mf][1], aq[mf][2], aq[mf][3], ad);
            }
#pragma unroll
            for (int p = 0; p < 4; p++) {
                const u32 kd = kb_ + K_O + (u32)(((p * 16 + (lane & 15)) * STR
                                      + kf * 16 + (lane >> 4) * 8) * 2);
                u32 t0, t1, t2, t3;
                u32 bk0[2], bk1[2];
                ldsm4(t0, t1, t2, t3, kd);
                bk0[0] = t0; bk0[1] = t2; bk1[0] = t1; bk1[1] = t3;
#pragma unroll
                for (int mf = 0; mf < 2; mf++) {
                    mma16816(s[mf][2 * p], aq[mf], bk0);
                    mma16816(s[mf][2 * p + 1], aq[mf], bk1);
                }
            }
        }

        const int kbase = t << 6;
#pragma unroll
        for (int mf = 0; mf < 2; mf++) {
#pragma unroll
            for (int hl = 0; hl < 2; hl++) {
                const int qi = q0 + wm + mf * 16 + g + hl * 8;
                const int idx = mf * 2 + hl;
                float mx = -1e30f;
#pragma unroll
                for (int nf = 0; nf < 8; nf++) {
                    const int c0 = kbase + nf * 8 + qd * 2;
                    float s0 = s[mf][nf][hl * 2];
                    float s1 = s[mf][nf][hl * 2 + 1];
                    if (c0 > qi) s0 = -1e30f;
                    if (c0 + 1 > qi) s1 = -1e30f;
                    s[mf][nf][hl * 2] = s0;
                    s[mf][nf][hl * 2 + 1] = s1;
                    mx = fmaxf(mx, fmaxf(s0, s1));
                }
                mx = fmaxf(mx, __shfl_xor_sync(0xffffffffu, mx, 1));
                mx = fmaxf(mx, __shfl_xor_sync(0xffffffffu, mx, 2));
                const float mnew = fmaxf(mrow[idx], mx);
                const float sc = __expf(mrow[idx] - mnew);
                mrow[idx] = mnew;
                float ps = 0.f;
#pragma unroll
                for (int nf = 0; nf < 8; nf++) {
                    float p0 = __expf(s[mf][nf][hl * 2] - mnew);
                    float p1 = __expf(s[mf][nf][hl * 2 + 1] - mnew);
                    s[mf][nf][hl * 2] = p0;
                    s[mf][nf][hl * 2 + 1] = p1;
                    ps += p0 + p1;
                    o[mf][nf][hl * 2] *= sc;
                    o[mf][nf][hl * 2 + 1] *= sc;
                }
                ps += __shfl_xor_sync(0xffffffffu, ps, 1);
                ps += __shfl_xor_sync(0xffffffffu, ps, 2);
                lrow[idx] = lrow[idx] * sc + ps;
            }
        }

#pragma unroll
        for (int kg2 = 0; kg2 < 4; kg2++) {
            u32 ap[2][4];
#pragma unroll
            for (int mf = 0; mf < 2; mf++) {
                ap[mf][0] = packh(s[mf][2 * kg2][0], s[mf][2 * kg2][1]);
                ap[mf][1] = packh(s[mf][2 * kg2][2], s[mf][2 * kg2][3]);
                ap[mf][2] = packh(s[mf][2 * kg2 + 1][0], s[mf][2 * kg2 + 1][1]);
                ap[mf][3] = packh(s[mf][2 * kg2 + 1][2], s[mf][2 * kg2 + 1][3]);
            }
#pragma unroll
            for (int dp = 0; dp < 4; dp++) {
                const u32 vrow = kb_ + V_O
                    + (u32)(((kg2 * 16 + (lane & 7) + ((lane >> 3) & 1) * 8) * STR
                             + dp * 16 + (lane >> 4) * 8) * 2);
                u32 t0, t1, t2, t3;
                u32 bv0[2], bv1[2];
                ldsm4t(t0, t1, t2, t3, vrow);
                bv0[0] = t0; bv0[1] = t1; bv1[0] = t2; bv1[1] = t3;
#pragma unroll
                for (int mf = 0; mf < 2; mf++) {
                    mma16816(o[mf][2 * dp], ap[mf], bv0);
                    mma16816(o[mf][2 * dp + 1], ap[mf], bv1);
                }
            }
        }
        __syncthreads();
    }

    // ----- epilogue: valid rows -> attention output; invalid -> mean(V) -----
#pragma unroll
    for (int mf = 0; mf < 2; mf++) {
#pragma unroll
        for (int hl = 0; hl < 2; hl++) {
            const int idx = mf * 2 + hl;
            const int qi = q0 + wm + mf * 16 + g + hl * 8;
            const size_t ebase = (size_t)(b * LDIM + qi) * 512 + h * 32;
            if (qi < sl) {
                const float inv = 1.f / lrow[idx];
#pragma unroll
                for (int nf = 0; nf < 8; nf++) {
                    const float o0 = o[mf][nf][hl * 2] * inv;
                    const float o1 = o[mf][nf][hl * 2 + 1] * inv;
                    ctx[ebase + nf * 4 + qd] = packh(o0, o1);
                }
            } else {
#pragma unroll
                for (int nf = 0; nf < 8; nf++) {
                    const int col = h * 64 + nf * 8 + qd * 2;
                    ctx[ebase + nf * 4 + qd] = packh(mv[b * 1024 + col],
                                                     mv[b * 1024 + col + 1]);
                }
            }
        }
    }
}

// ---------------------------------------------------------------------------
extern "C" void kernel_launch(void* const* d_in, const int* in_sizes, int n_in,
                              void* d_out, int out_size)
{
    const float* hs = (const float*)d_in[0];
    const int* sl   = (const int*)d_in[1];
    const float* Wq = (const float*)d_in[2];
    const float* bq = (const float*)d_in[3];
    const float* Wk = (const float*)d_in[4];
    const float* Wv = (const float*)d_in[5];
    const float* bv = (const float*)d_in[6];
    const float* Wo = (const float*)d_in[7];
    const float* bo = (const float*)d_in[8];
    float* out = (float*)d_out;

    __half *q, *k, *v, *hsx, *ctx, *wx;
    float* mv;
    cudaGetSymbolAddress((void**)&q, g_q);
    cudaGetSymbolAddress((void**)&k, g_k);
    cudaGetSymbolAddress((void**)&v, g_v);
    cudaGetSymbolAddress((void**)&hsx, g_hs);
    cudaGetSymbolAddress((void**)&ctx, g_ctx);
    cudaGetSymbolAddress((void**)&wx, g_w);
    cudaGetSymbolAddress((void**)&mv, g_meanv);

    cudaFuncSetAttribute(gemm_h, cudaFuncAttributeMaxDynamicSharedMemorySize, G_SMEM);
    cudaFuncSetAttribute(attn_mma, cudaFuncAttributeMaxDynamicSharedMemorySize, ATT_SMEM);

    // fused conversion: hs + 4 weight matrices, one launch
    conv_all<<<(HS4 + 4 * W4) / 256, 256>>>(hs, Wq, Wk, Wv, Wo, hsx, wx);

    // fused QKV: grid (4, 32, 3)
    dim3 g3(EDIM / 256, MDIM / 128, 3);
    gemm_h<<<g3, 512, G_SMEM>>>(hsx, wx, bq, bv, nullptr,
                                (u32*)q, (u32*)k, (u32*)v, 1);

    // single-launch mean(V)
    meanv_kernel<<<BDIM * HDIM, 1024>>>(mv);

    // attention (handles invalid rows inline)
    dim3 ga(LDIM / 128, BDIM * HDIM);   // (16, 32)
    attn_mma<<<ga, 128, ATT_SMEM>>>(sl, mv, (u32*)ctx);

    // O projection: grid (4, 32, 1), Wbase = Wo
    dim3 g1(EDIM / 256, MDIM / 128, 1);
    gemm_h<<<g1, 512, G_SMEM>>>(ctx, wx + 3 * (size_t)WSZ, bo, nullptr, out,
                                nullptr, nullptr, nullptr, 0);
}

// round 13
// speedup vs baseline: 1.0425x; 1.0425x over previous
#include <cuda_runtime.h>
#include <cuda_fp16.h>
#include <cstdint>
#include <math.h>

typedef unsigned int u32;

#define BDIM 2
#define LDIM 2048
#define EDIM 1024
#define HDIM 16
#define DDIM 64
#define MDIM (BDIM * LDIM)   // 4096
#define WSZ (EDIM * EDIM)

// ---------------- scratch (device globals; allocation is forbidden) --------
__device__ __half g_q[BDIM * HDIM * LDIM * DDIM];   // [B,H,L,D]
__device__ __half g_k[BDIM * HDIM * LDIM * DDIM];
__device__ __half g_v[BDIM * HDIM * LDIM * DDIM];
__device__ __half g_hs[MDIM * EDIM];
__device__ __half g_ctx[MDIM * EDIM];               // [B,L,E]
__device__ __half g_w[4 * EDIM * EDIM];             // Wq,Wk,Wv,Wo
__device__ float g_meanv[BDIM * HDIM * DDIM];       // [B,H,D]

// ---------------------------------------------------------------------------
// helpers
// ---------------------------------------------------------------------------
__device__ __forceinline__ u32 packh(float lo, float hi) {
    u32 d;
    asm("cvt.rn.f16x2.f32 %0, %1, %2;" : "=r"(d) : "f"(hi), "f"(lo));
    return d;
}

__device__ __forceinline__ void cpasync16(u32 dst, const void* src) {
    asm volatile("cp.async.cg.shared.global [%0], [%1], 16;\n" :: "r"(dst), "l"(src));
}
__device__ __forceinline__ void cp_commit() { asm volatile("cp.async.commit_group;\n"); }
__device__ __forceinline__ void cp_wait1() { asm volatile("cp.async.wait_group 1;\n"); }
__device__ __forceinline__ void cp_wait0() { asm volatile("cp.async.wait_group 0;\n"); }

__device__ __forceinline__ void ldsm4(u32& r0, u32& r1, u32& r2, u32& r3, u32 addr) {
    asm volatile("ldmatrix.sync.aligned.m8n8.x4.shared.b16 {%0,%1,%2,%3}, [%4];"
        : "=r"(r0), "=r"(r1), "=r"(r2), "=r"(r3) : "r"(addr));
}
__device__ __forceinline__ void ldsm4t(u32& r0, u32& r1, u32& r2, u32& r3, u32 addr) {
    asm volatile("ldmatrix.sync.aligned.m8n8.x4.trans.shared.b16 {%0,%1,%2,%3}, [%4];"
        : "=r"(r0), "=r"(r1), "=r"(r2), "=r"(r3) : "r"(addr));
}
__device__ __forceinline__ void mma16816(float* acc, const u32* a, const u32* b) {
    asm volatile("mma.sync.aligned.m16n8k16.row.col.f32.f16.f16.f32 "
        "{%0,%1,%2,%3}, {%4,%5,%6,%7}, {%8,%9}, {%0,%1,%2,%3};"
        : "+f"(acc[0]), "+f"(acc[1]), "+f"(acc[2]), "+f"(acc[3])
        : "r"(a[0]), "r"(a[1]), "r"(a[2]), "r"(a[3]), "r"(b[0]), "r"(b[1]));
}

// ---------------------------------------------------------------------------
// Fused fp32 -> fp16 convert for hidden_states + all 4 weight matrices
// ---------------------------------------------------------------------------
#define HS4 (MDIM * EDIM / 4)
#define W4 (WSZ / 4)

__global__ __launch_bounds__(256)
void conv_all(const float* __restrict__ hs,
              const float* __restrict__ w0, const float* __restrict__ w1,
              const float* __restrict__ w2, const float* __restrict__ w3,
              __half* __restrict__ ohs, __half* __restrict__ ow)
{
    int i = blockIdx.x * blockDim.x + threadIdx.x;
    const float* src;
    uint2* dst;
    int j;
    if (i < HS4) {
        src = hs; j = i; dst = (uint2*)ohs + i;
    } else {
        const int t = i - HS4;
        const int m = t / W4;
        j = t - m * W4;
        src = (m == 0) ? w0 : (m == 1) ? w1 : (m == 2) ? w2 : w3;
        dst = (uint2*)ow + t;
    }
    float4 v = ((const float4*)src)[j];
    uint2 hv;
    hv.x = packh(v.x, v.y);
    hv.y = packh(v.z, v.w);
    *dst = hv;
}

// ---------------------------------------------------------------------------
// mean(V): single-kernel deterministic reduction. grid=32, block=1024.
// ---------------------------------------------------------------------------
__global__ __launch_bounds__(1024)
void meanv_kernel(float* __restrict__ mv)
{
    __shared__ float red[1024];
    const int bh = blockIdx.x;
    const int tid = threadIdx.x;
    const int d = tid & 63;
    const int sub = tid >> 6;
    const __half* vb = g_v + (size_t)bh * LDIM * DDIM;
    const int l0 = sub * 128;
    float s = 0.f;
#pragma unroll 4
    for (int l = l0; l < l0 + 128; l++)
        s += __half2float(vb[(size_t)l * DDIM + d]);
    red[tid] = s;
    __syncthreads();
    if (tid < 64) {
        float t = 0.f;
#pragma unroll
        for (int k = 0; k < 16; k++)
            t += red[d + 64 * k];
        mv[bh * DDIM + d] = t * (1.0f / 2048.0f);
    }
}

// ---------------------------------------------------------------------------
// fp16 tensor-core NT GEMM, fused-QKV capable (round-10 validated).
// ---------------------------------------------------------------------------
#define SSTR 72
#define A_ARR (128 * SSTR * 2)
#define B_ARR (256 * SSTR * 2)
#define O_A 0
#define O_B A_ARR
#define STG (A_ARR + B_ARR)
#define G_SMEM (3 * STG)

__device__ __forceinline__ void g_issue(
    u32 sbase, int s, int k0, int tid,
    const __half* A, const __half* B, int bm, int bn)
{
    const u32 st = sbase + (u32)(s % 3) * STG;
#pragma unroll
    for (int i = 0; i < 2; i++) {
        const int c = tid + i * 512;
        const int row = c >> 3, ch = c & 7;
        const u32 so = (u32)(row * (SSTR * 2) + ch * 16);
        cpasync16(st + O_A + so, A + (size_t)(bm + row) * EDIM + k0 + ch * 8);
    }
#pragma unroll
    for (int i = 0; i < 4; i++) {
        const int c = tid + i * 512;
        const int row = c >> 3, ch = c & 7;
        const u32 so = (u32)(row * (SSTR * 2) + ch * 16);
        cpasync16(st + O_B + so, B + (size_t)(bn + row) * EDIM + k0 + ch * 8);
    }
    cp_commit();
}

extern "C" __global__ __launch_bounds__(512, 1)
void gemm_h(const __half* __restrict__ Ag, const __half* __restrict__ Wbase,
            const float* __restrict__ b0, const float* __restrict__ b2,
            float* __restrict__ out,
            u32* __restrict__ o0, u32* __restrict__ o1, u32* __restrict__ o2,
            int fused)
{
    extern __shared__ __align__(16) char dynsmem[];
    const u32 sbase = (u32)__cvta_generic_to_shared(dynsmem);
    const int bm = blockIdx.y * 128;
    const int bn = blockIdx.x * 256;
    const int z = blockIdx.z;
    const int tid = threadIdx.x;
    const int lane = tid & 31;
    const int wid = tid >> 5;
    const int wm = (wid & 3) * 32;
    const int wn = (wid >> 2) * 64;

    const __half* Bg = Wbase + (size_t)z * WSZ;
    const float* bias;
    float alpha;
    u32* outq;
    if (fused) {
        bias = (z == 0) ? b0 : ((z == 2) ? b2 : nullptr);
        alpha = (z == 0) ? 0.125f : 1.0f;
        outq = (z == 0) ? o0 : ((z == 1) ? o1 : o2);
    } else {
        bias = b0; alpha = 1.0f; outq = nullptr;
    }

    float acc[2][8][4];
#pragma unroll
    for (int i = 0; i < 2; i++)
#pragma unroll
        for (int j = 0; j < 8; j++)
#pragma unroll
            for (int c = 0; c < 4; c++) acc[i][j][c] = 0.f;

    const int lrA = wm + (lane & 15);
    const int lrB = wn + (lane & 15);
    const int lcol = (lane >> 4) * 8;

    const int NIT = EDIM / 64;
    g_issue(sbase, 0, 0, tid, Ag, Bg, bm, bn);
    g_issue(sbase, 1, 64, tid, Ag, Bg, bm, bn);

    for (int it = 0; it < NIT; it++) {
        if (it + 1 < NIT) cp_wait1(); else cp_wait0();
        __syncthreads();
        if (it + 2 < NIT)
            g_issue(sbase, it + 2, (it + 2) * 64, tid, Ag, Bg, bm, bn);

        const u32 st = sbase + (u32)(it % 3) * STG;
#pragma unroll
        for (int ks = 0; ks < 4; ks++) {
            const int kb = ks * 16;
            u32 ah[2][4];
#pragma unroll
            for (int mt = 0; mt < 2; mt++) {
                const u32 ad = st + O_A + (u32)((lrA + mt * 16) * SSTR + kb + lcol) * 2;
                ldsm4(ah[mt][0], ah[mt][1], ah[mt][2], ah[mt][3], ad);
            }
#pragma unroll
            for (int p = 0; p < 4; p++) {
                const u32 bd = st + O_B + (u32)((lrB + p * 16) * SSTR + kb + lcol) * 2;
                u32 t0, t1, t2, t3;
                u32 b0r[2], b1r[2];
                ldsm4(t0, t1, t2, t3, bd);
                b0r[0] = t0; b0r[1] = t2; b1r[0] = t1; b1r[1] = t3;
#pragma unroll
                for (int mt = 0; mt < 2; mt++) {
                    mma16816(acc[mt][2 * p], ah[mt], b0r);
                    mma16816(acc[mt][2 * p + 1], ah[mt], b1r);
                }
            }
        }
        __syncthreads();
    }

#pragma unroll
    for (int mt = 0; mt < 2; mt++) {
#pragma unroll
        for (int nt = 0; nt < 8; nt++) {
#pragma unroll
            for (int r = 0; r < 2; r++) {
                const int row = bm + wm + mt * 16 + (lane >> 2) + r * 8;
                const int col0 = bn + wn + nt * 8 + (lane & 3) * 2;
                float v0 = acc[mt][nt][r * 2 + 0];
                float v1 = acc[mt][nt][r * 2 + 1];
                if (bias) { v0 += bias[col0]; v1 += bias[col0 + 1]; }
                v0 *= alpha; v1 *= alpha;
                const int b = row >> 11;
                const int l = row & (LDIM - 1);
                if (fused) {
                    const int h = col0 >> 6;
                    const int d = col0 & (DDIM - 1);
                    const size_t e = (((size_t)(b * HDIM + h) * LDIM) + l) * DDIM + d;
                    outq[e >> 1] = packh(v0, v1);
                } else {
                    out[(size_t)row * EDIM + col0] = v0;
                    out[(size_t)row * EDIM + col0 + 1] = v1;
                }
            }
        }
    }
}

// ---------------------------------------------------------------------------
// fp16 tensor-core flash attention, 256 threads / 8 warps, warp = 16 query
// rows (reduced per-thread state -> higher occupancy). Invalid rows inline.
// ---------------------------------------------------------------------------
#define STR 72
#define Q_OFF 0
#define ST_BASE (128 * STR * 2)           // 18432
#define KT_B (64 * STR * 2)               // 9216
#define K_O 0
#define V_O KT_B
#define ST_SZ (2 * KT_B)                  // 18432
#define ATT_SMEM (ST_BASE + 2 * ST_SZ)    // 55296

__device__ __forceinline__ void attn_issue_kv(u32 base, int kbase, int tid,
                                              const __half* kg, const __half* vg)
{
    // 64 rows x 8 chunks x 2 arrays = 1024 chunks, 256 threads -> 4 each
    const int row = tid >> 2;
    const int c0 = (tid & 3) * 2;
#pragma unroll
    for (int c = 0; c < 2; c++) {
        const int ch = c0 + c;
        const u32 off = (u32)((row * STR + ch * 8) * 2);
        const size_t src = (size_t)(kbase + row) * DDIM + ch * 8;
        cpasync16(base + K_O + off, kg + src);
        cpasync16(base + V_O + off, vg + src);
    }
}

__global__ __launch_bounds__(256)
void attn_mma(const int* __restrict__ seq_len, const float* __restrict__ mv,
              u32* __restrict__ ctx)
{
    extern __shared__ __align__(16) char sm[];
    const u32 sb = (u32)__cvta_generic_to_shared(sm);
    const int bh = blockIdx.y;
    const int b = bh >> 4;
    const int h = bh & (HDIM - 1);
    const int qt = (int)gridDim.x - 1 - (int)blockIdx.x;
    const int q0 = qt * 128;
    const int sl = seq_len[b];
    const int tid = threadIdx.x;

    if (q0 >= sl) {
        // fully invalid block: write mean(V) rows and exit
        const int cp = tid & 31;
        const int r0 = tid >> 5;          // 0..7
        const u32 mval = packh(mv[b * 1024 + h * 64 + cp * 2],
                               mv[b * 1024 + h * 64 + cp * 2 + 1]);
        for (int r = r0; r < 128; r += 8) {
            const size_t e = (size_t)(b * LDIM + q0 + r) * 512 + h * 32 + cp;
            ctx[e] = mval;
        }
        return;
    }

    const int lane = tid & 31;
    const int w = tid >> 5;               // 0..7
    const int wm = w * 16;                // 16 query rows per warp
    const int g = lane >> 2;
    const int qd = lane & 3;

    const size_t hoff = (size_t)bh * LDIM * DDIM;
    const __half* qg = g_q + hoff;
    const __half* kg = g_k + hoff;
    const __half* vg = g_v + hoff;

    {
        // Q: 128 rows x 8 chunks = 1024 chunks, 256 threads -> 4 each
        const int row = tid >> 1;
        const int c0 = (tid & 1) * 4;
        const size_t src = (size_t)(q0 + row) * DDIM;
#pragma unroll
        for (int c = 0; c < 4; c++)
            cpasync16(sb + Q_OFF + (u32)((row * STR + (c0 + c) * 8) * 2),
                      qg + src + (c0 + c) * 8);
    }
    attn_issue_kv(sb + ST_BASE, 0, tid, kg, vg);
    cp_commit();

    const int qend = min(q0 + 127, sl - 1);
    const int ntiles = (qend >> 6) + 1;

    float o[8][4];
    float mrow[2], lrow[2];
#pragma unroll
    for (int j = 0; j < 8; j++)
#pragma unroll
        for (int c = 0; c < 4; c++) o[j][c] = 0.f;
    mrow[0] = mrow[1] = -1e30f;
    lrow[0] = lrow[1] = 0.f;

    for (int t = 0; t < ntiles; t++) {
        if (t + 1 < ntiles) {
            attn_issue_kv(sb + ST_BASE + (u32)((t + 1) & 1) * ST_SZ, (t + 1) << 6,
                          tid, kg, vg);
            cp_commit();
            cp_wait1();
        } else {
            cp_wait0();
        }
        __syncthreads();

        const u32 kb_ = sb + ST_BASE + (u32)(t & 1) * ST_SZ;

        // ----- S = Q K^T -----
        float s[8][4];
#pragma unroll
        for (int j = 0; j < 8; j++)
#pragma unroll
            for (int c = 0; c < 4; c++) s[j][c] = 0.f;

#pragma unroll
        for (int kf = 0; kf < 4; kf++) {
            u32 aq[4];
            const u32 ad = sb + Q_OFF + (u32)(((wm + (lane & 15)) * STR
                                  + kf * 16 + (lane >> 4) * 8) * 2);
            ldsm4(aq[0], aq[1], aq[2], aq[3], ad);
#pragma unroll
            for (int p = 0; p < 4; p++) {
                const u32 kd = kb_ + K_O + (u32)(((p * 16 + (lane & 15)) * STR
                                      + kf * 16 + (lane >> 4) * 8) * 2);
                u32 t0, t1, t2, t3;
                u32 bk0[2], bk1[2];
                ldsm4(t0, t1, t2, t3, kd);
                bk0[0] = t0; bk0[1] = t2; bk1[0] = t1; bk1[1] = t3;
                mma16816(s[2 * p], aq, bk0);
                mma16816(s[2 * p + 1], aq, bk1);
            }
        }

        // ----- causal mask + online softmax -----
        const int kbase = t << 6;
#pragma unroll
        for (int hl = 0; hl < 2; hl++) {
            const int qi = q0 + wm + g + hl * 8;
            float mx = -1e30f;
#pragma unroll
            for (int nf = 0; nf < 8; nf++) {
                const int c0 = kbase + nf * 8 + qd * 2;
                float s0 = s[nf][hl * 2];
                float s1 = s[nf][hl * 2 + 1];
                if (c0 > qi) s0 = -1e30f;
                if (c0 + 1 > qi) s1 = -1e30f;
                s[nf][hl * 2] = s0;
                s[nf][hl * 2 + 1] = s1;
                mx = fmaxf(mx, fmaxf(s0, s1));
            }
            mx = fmaxf(mx, __shfl_xor_sync(0xffffffffu, mx, 1));
            mx = fmaxf(mx, __shfl_xor_sync(0xffffffffu, mx, 2));
            const float mnew = fmaxf(mrow[hl], mx);
            const float sc = __expf(mrow[hl] - mnew);
            mrow[hl] = mnew;
            float ps = 0.f;
#pragma unroll
            for (int nf = 0; nf < 8; nf++) {
                float p0 = __expf(s[nf][hl * 2] - mnew);
                float p1 = __expf(s[nf][hl * 2 + 1] - mnew);
                s[nf][hl * 2] = p0;
                s[nf][hl * 2 + 1] = p1;
                ps += p0 + p1;
                o[nf][hl * 2] *= sc;
                o[nf][hl * 2 + 1] *= sc;
            }
            ps += __shfl_xor_sync(0xffffffffu, ps, 1);
            ps += __shfl_xor_sync(0xffffffffu, ps, 2);
            lrow[hl] = lrow[hl] * sc + ps;
        }

        // ----- O += P V -----
#pragma unroll
        for (int kg2 = 0; kg2 < 4; kg2++) {
            u32 ap[4];
            ap[0] = packh(s[2 * kg2][0], s[2 * kg2][1]);
            ap[1] = packh(s[2 * kg2][2], s[2 * kg2][3]);
            ap[2] = packh(s[2 * kg2 + 1][0], s[2 * kg2 + 1][1]);
            ap[3] = packh(s[2 * kg2 + 1][2], s[2 * kg2 + 1][3]);
#pragma unroll
            for (int dp = 0; dp < 4; dp++) {
                const u32 vrow = kb_ + V_O
                    + (u32)(((kg2 * 16 + (lane & 7) + ((lane >> 3) & 1) * 8) * STR
                             + dp * 16 + (lane >> 4) * 8) * 2);
                u32 t0, t1, t2, t3;
                u32 bv0[2], bv1[2];
                ldsm4t(t0, t1, t2, t3, vrow);
                bv0[0] = t0; bv0[1] = t1; bv1[0] = t2; bv1[1] = t3;
                mma16816(o[2 * dp], ap, bv0);
                mma16816(o[2 * dp + 1], ap, bv1);
            }
        }
        __syncthreads();
    }

    // ----- epilogue: valid rows -> attention output; invalid -> mean(V) -----
#pragma unroll
    for (int hl = 0; hl < 2; hl++) {
        const int qi = q0 + wm + g + hl * 8;
        const size_t ebase = (size_t)(b * LDIM + qi) * 512 + h * 32;
        if (qi < sl) {
            const float inv = 1.f / lrow[hl];
#pragma unroll
            for (int nf = 0; nf < 8; nf++) {
                const float o0 = o[nf][hl * 2] * inv;
                const float o1 = o[nf][hl * 2 + 1] * inv;
                ctx[ebase + nf * 4 + qd] = packh(o0, o1);
            }
        } else {
#pragma unroll
            for (int nf = 0; nf < 8; nf++) {
                const int col = h * 64 + nf * 8 + qd * 2;
                ctx[ebase + nf * 4 + qd] = packh(mv[b * 1024 + col],
                                                 mv[b * 1024 + col + 1]);
            }
        }
    }
}

// ---------------------------------------------------------------------------
extern "C" void kernel_launch(void* const* d_in, const int* in_sizes, int n_in,
                              void* d_out, int out_size)
{
    const float* hs = (const float*)d_in[0];
    const int* sl   = (const int*)d_in[1];
    const float* Wq = (const float*)d_in[2];
    const float* bq = (const float*)d_in[3];
    const float* Wk = (const float*)d_in[4];
    const float* Wv = (const float*)d_in[5];
    const float* bv = (const float*)d_in[6];
    const float* Wo = (const float*)d_in[7];
    const float* bo = (const float*)d_in[8];
    float* out = (float*)d_out;

    __half *q, *k, *v, *hsx, *ctx, *wx;
    float* mv;
    cudaGetSymbolAddress((void**)&q, g_q);
    cudaGetSymbolAddress((void**)&k, g_k);
    cudaGetSymbolAddress((void**)&v, g_v);
    cudaGetSymbolAddress((void**)&hsx, g_hs);
    cudaGetSymbolAddress((void**)&ctx, g_ctx);
    cudaGetSymbolAddress((void**)&wx, g_w);
    cudaGetSymbolAddress((void**)&mv, g_meanv);

    cudaFuncSetAttribute(gemm_h, cudaFuncAttributeMaxDynamicSharedMemorySize, G_SMEM);
    cudaFuncSetAttribute(attn_mma, cudaFuncAttributeMaxDynamicSharedMemorySize, ATT_SMEM);

    conv_all<<<(HS4 + 4 * W4) / 256, 256>>>(hs, Wq, Wk, Wv, Wo, hsx, wx);

    dim3 g3(EDIM / 256, MDIM / 128, 3);
    gemm_h<<<g3, 512, G_SMEM>>>(hsx, wx, bq, bv, nullptr,
                                (u32*)q, (u32*)k, (u32*)v, 1);

    meanv_kernel<<<BDIM * HDIM, 1024>>>(mv);

    dim3 ga(LDIM / 128, BDIM * HDIM);   // (16, 32)
    attn_mma<<<ga, 256, ATT_SMEM>>>(sl, mv, (u32*)ctx);

    dim3 g1(EDIM / 256, MDIM / 128, 1);
    gemm_h<<<g1, 512, G_SMEM>>>(ctx, wx + 3 * (size_t)WSZ, bo, nullptr, out,
                                nullptr, nullptr, nullptr, 0);
}

// round 14
// speedup vs baseline: 1.0749x; 1.0310x over previous
#include <cuda_runtime.h>
#include <cuda_fp16.h>
#include <cstdint>
#include <math.h>

typedef unsigned int u32;

#define BDIM 2
#define LDIM 2048
#define EDIM 1024
#define HDIM 16
#define DDIM 64
#define MDIM (BDIM * LDIM)   // 4096
#define WSZ (EDIM * EDIM)

// ---------------- scratch (device globals; allocation is forbidden) --------
__device__ __half g_q[BDIM * HDIM * LDIM * DDIM];   // [B,H,L,D]
__device__ __half g_k[BDIM * HDIM * LDIM * DDIM];
__device__ __half g_v[BDIM * HDIM * LDIM * DDIM];
__device__ __half g_hs[MDIM * EDIM];
__device__ __half g_ctx[MDIM * EDIM];               // [B,L,E]
__device__ __half g_w[4 * EDIM * EDIM];             // Wq,Wk,Wv,Wo
__device__ float g_meanv[BDIM * HDIM * DDIM];       // [B,H,D]

// ---------------------------------------------------------------------------
// helpers
// ---------------------------------------------------------------------------
__device__ __forceinline__ u32 packh(float lo, float hi) {
    u32 d;
    asm("cvt.rn.f16x2.f32 %0, %1, %2;" : "=r"(d) : "f"(hi), "f"(lo));
    return d;
}
__device__ __forceinline__ float fexp2(float x) {
    float r;
    asm("ex2.approx.ftz.f32 %0, %1;" : "=f"(r) : "f"(x));
    return r;
}

__device__ __forceinline__ void cpasync16(u32 dst, const void* src) {
    asm volatile("cp.async.cg.shared.global [%0], [%1], 16;\n" :: "r"(dst), "l"(src));
}
__device__ __forceinline__ void cp_commit() { asm volatile("cp.async.commit_group;\n"); }
__device__ __forceinline__ void cp_wait1() { asm volatile("cp.async.wait_group 1;\n"); }
__device__ __forceinline__ void cp_wait0() { asm volatile("cp.async.wait_group 0;\n"); }

__device__ __forceinline__ void ldsm4(u32& r0, u32& r1, u32& r2, u32& r3, u32 addr) {
    asm volatile("ldmatrix.sync.aligned.m8n8.x4.shared.b16 {%0,%1,%2,%3}, [%4];"
        : "=r"(r0), "=r"(r1), "=r"(r2), "=r"(r3) : "r"(addr));
}
__device__ __forceinline__ void ldsm4t(u32& r0, u32& r1, u32& r2, u32& r3, u32 addr) {
    asm volatile("ldmatrix.sync.aligned.m8n8.x4.trans.shared.b16 {%0,%1,%2,%3}, [%4];"
        : "=r"(r0), "=r"(r1), "=r"(r2), "=r"(r3) : "r"(addr));
}
__device__ __forceinline__ void mma16816(float* acc, const u32* a, const u32* b) {
    asm volatile("mma.sync.aligned.m16n8k16.row.col.f32.f16.f16.f32 "
        "{%0,%1,%2,%3}, {%4,%5,%6,%7}, {%8,%9}, {%0,%1,%2,%3};"
        : "+f"(acc[0]), "+f"(acc[1]), "+f"(acc[2]), "+f"(acc[3])
        : "r"(a[0]), "r"(a[1]), "r"(a[2]), "r"(a[3]), "r"(b[0]), "r"(b[1]));
}

// ---------------------------------------------------------------------------
// Fused fp32 -> fp16 convert for hidden_states + all 4 weight matrices
// ---------------------------------------------------------------------------
#define HS4 (MDIM * EDIM / 4)
#define W4 (WSZ / 4)

__global__ __launch_bounds__(256)
void conv_all(const float* __restrict__ hs,
              const float* __restrict__ w0, const float* __restrict__ w1,
              const float* __restrict__ w2, const float* __restrict__ w3,
              __half* __restrict__ ohs, __half* __restrict__ ow)
{
    int i = blockIdx.x * blockDim.x + threadIdx.x;
    const float* src;
    uint2* dst;
    int j;
    if (i < HS4) {
        src = hs; j = i; dst = (uint2*)ohs + i;
    } else {
        const int t = i - HS4;
        const int m = t / W4;
        j = t - m * W4;
        src = (m == 0) ? w0 : (m == 1) ? w1 : (m == 2) ? w2 : w3;
        dst = (uint2*)ow + t;
    }
    float4 v = ((const float4*)src)[j];
    uint2 hv;
    hv.x = packh(v.x, v.y);
    hv.y = packh(v.z, v.w);
    *dst = hv;
}

// ---------------------------------------------------------------------------
// mean(V): single-kernel deterministic reduction. grid=32, block=1024.
// ---------------------------------------------------------------------------
__global__ __launch_bounds__(1024)
void meanv_kernel(float* __restrict__ mv)
{
    __shared__ float red[1024];
    const int bh = blockIdx.x;
    const int tid = threadIdx.x;
    const int d = tid & 63;
    const int sub = tid >> 6;
    const __half* vb = g_v + (size_t)bh * LDIM * DDIM;
    const int l0 = sub * 128;
    float s = 0.f;
#pragma unroll 4
    for (int l = l0; l < l0 + 128; l++)
        s += __half2float(vb[(size_t)l * DDIM + d]);
    red[tid] = s;
    __syncthreads();
    if (tid < 64) {
        float t = 0.f;
#pragma unroll
        for (int k = 0; k < 16; k++)
            t += red[d + 64 * k];
        mv[bh * DDIM + d] = t * (1.0f / 2048.0f);
    }
}

// ---------------------------------------------------------------------------
// fp16 tensor-core NT GEMM, fused-QKV capable (round-10 validated).
// ---------------------------------------------------------------------------
#define SSTR 72
#define A_ARR (128 * SSTR * 2)
#define B_ARR (256 * SSTR * 2)
#define O_A 0
#define O_B A_ARR
#define STG (A_ARR + B_ARR)
#define G_SMEM (3 * STG)

__device__ __forceinline__ void g_issue(
    u32 sbase, int s, int k0, int tid,
    const __half* A, const __half* B, int bm, int bn)
{
    const u32 st = sbase + (u32)(s % 3) * STG;
#pragma unroll
    for (int i = 0; i < 2; i++) {
        const int c = tid + i * 512;
        const int row = c >> 3, ch = c & 7;
        const u32 so = (u32)(row * (SSTR * 2) + ch * 16);
        cpasync16(st + O_A + so, A + (size_t)(bm + row) * EDIM + k0 + ch * 8);
    }
#pragma unroll
    for (int i = 0; i < 4; i++) {
        const int c = tid + i * 512;
        const int row = c >> 3, ch = c & 7;
        const u32 so = (u32)(row * (SSTR * 2) + ch * 16);
        cpasync16(st + O_B + so, B + (size_t)(bn + row) * EDIM + k0 + ch * 8);
    }
    cp_commit();
}

extern "C" __global__ __launch_bounds__(512, 1)
void gemm_h(const __half* __restrict__ Ag, const __half* __restrict__ Wbase,
            const float* __restrict__ b0, const float* __restrict__ b2,
            float* __restrict__ out,
            u32* __restrict__ o0, u32* __restrict__ o1, u32* __restrict__ o2,
            int fused)
{
    extern __shared__ __align__(16) char dynsmem[];
    const u32 sbase = (u32)__cvta_generic_to_shared(dynsmem);
    const int bm = blockIdx.y * 128;
    const int bn = blockIdx.x * 256;
    const int z = blockIdx.z;
    const int tid = threadIdx.x;
    const int lane = tid & 31;
    const int wid = tid >> 5;
    const int wm = (wid & 3) * 32;
    const int wn = (wid >> 2) * 64;

    const __half* Bg = Wbase + (size_t)z * WSZ;
    const float* bias;
    float alpha;
    u32* outq;
    if (fused) {
        bias = (z == 0) ? b0 : ((z == 2) ? b2 : nullptr);
        // Q scaled by D^-0.5 * log2(e) so softmax can use ex2 directly
        alpha = (z == 0) ? 0.125f * 1.4426950408889634f : 1.0f;
        outq = (z == 0) ? o0 : ((z == 1) ? o1 : o2);
    } else {
        bias = b0; alpha = 1.0f; outq = nullptr;
    }

    float acc[2][8][4];
#pragma unroll
    for (int i = 0; i < 2; i++)
#pragma unroll
        for (int j = 0; j < 8; j++)
#pragma unroll
            for (int c = 0; c < 4; c++) acc[i][j][c] = 0.f;

    const int lrA = wm + (lane & 15);
    const int lrB = wn + (lane & 15);
    const int lcol = (lane >> 4) * 8;

    const int NIT = EDIM / 64;
    g_issue(sbase, 0, 0, tid, Ag, Bg, bm, bn);
    g_issue(sbase, 1, 64, tid, Ag, Bg, bm, bn);

    for (int it = 0; it < NIT; it++) {
        if (it + 1 < NIT) cp_wait1(); else cp_wait0();
        __syncthreads();
        if (it + 2 < NIT)
            g_issue(sbase, it + 2, (it + 2) * 64, tid, Ag, Bg, bm, bn);

        const u32 st = sbase + (u32)(it % 3) * STG;
#pragma unroll
        for (int ks = 0; ks < 4; ks++) {
            const int kb = ks * 16;
            u32 ah[2][4];
#pragma unroll
            for (int mt = 0; mt < 2; mt++) {
                const u32 ad = st + O_A + (u32)((lrA + mt * 16) * SSTR + kb + lcol) * 2;
                ldsm4(ah[mt][0], ah[mt][1], ah[mt][2], ah[mt][3], ad);
            }
#pragma unroll
            for (int p = 0; p < 4; p++) {
                const u32 bd = st + O_B + (u32)((lrB + p * 16) * SSTR + kb + lcol) * 2;
                u32 t0, t1, t2, t3;
                u32 b0r[2], b1r[2];
                ldsm4(t0, t1, t2, t3, bd);
                b0r[0] = t0; b0r[1] = t2; b1r[0] = t1; b1r[1] = t3;
#pragma unroll
                for (int mt = 0; mt < 2; mt++) {
                    mma16816(acc[mt][2 * p], ah[mt], b0r);
                    mma16816(acc[mt][2 * p + 1], ah[mt], b1r);
                }
            }
        }
        __syncthreads();
    }

#pragma unroll
    for (int mt = 0; mt < 2; mt++) {
#pragma unroll
        for (int nt = 0; nt < 8; nt++) {
#pragma unroll
            for (int r = 0; r < 2; r++) {
                const int row = bm + wm + mt * 16 + (lane >> 2) + r * 8;
                const int col0 = bn + wn + nt * 8 + (lane & 3) * 2;
                float v0 = acc[mt][nt][r * 2 + 0];
                float v1 = acc[mt][nt][r * 2 + 1];
                if (bias) { v0 += bias[col0]; v1 += bias[col0 + 1]; }
                v0 *= alpha; v1 *= alpha;
                const int b = row >> 11;
                const int l = row & (LDIM - 1);
                if (fused) {
                    const int h = col0 >> 6;
                    const int d = col0 & (DDIM - 1);
                    const size_t e = (((size_t)(b * HDIM + h) * LDIM) + l) * DDIM + d;
                    outq[e >> 1] = packh(v0, v1);
                } else {
                    out[(size_t)row * EDIM + col0] = v0;
                    out[(size_t)row * EDIM + col0 + 1] = v1;
                }
            }
        }
    }
}

// ---------------------------------------------------------------------------
// fp16 tensor-core flash attention, 256 threads / 8 warps, warp = 16 rows.
// exp2-domain softmax (Q pre-scaled by log2e); interior tiles skip masking.
// ---------------------------------------------------------------------------
#define STR 72
#define Q_OFF 0
#define ST_BASE (128 * STR * 2)           // 18432
#define KT_B (64 * STR * 2)               // 9216
#define K_O 0
#define V_O KT_B
#define ST_SZ (2 * KT_B)                  // 18432
#define ATT_SMEM (ST_BASE + 2 * ST_SZ)    // 55296

__device__ __forceinline__ void attn_issue_kv(u32 base, int kbase, int tid,
                                              const __half* kg, const __half* vg)
{
    const int row = tid >> 2;
    const int c0 = (tid & 3) * 2;
#pragma unroll
    for (int c = 0; c < 2; c++) {
        const int ch = c0 + c;
        const u32 off = (u32)((row * STR + ch * 8) * 2);
        const size_t src = (size_t)(kbase + row) * DDIM + ch * 8;
        cpasync16(base + K_O + off, kg + src);
        cpasync16(base + V_O + off, vg + src);
    }
}

__global__ __launch_bounds__(256)
void attn_mma(const int* __restrict__ seq_len, const float* __restrict__ mv,
              u32* __restrict__ ctx)
{
    extern __shared__ __align__(16) char sm[];
    const u32 sb = (u32)__cvta_generic_to_shared(sm);
    const int bh = blockIdx.y;
    const int b = bh >> 4;
    const int h = bh & (HDIM - 1);
    const int qt = (int)gridDim.x - 1 - (int)blockIdx.x;
    const int q0 = qt * 128;
    const int sl = seq_len[b];
    const int tid = threadIdx.x;

    if (q0 >= sl) {
        const int cp = tid & 31;
        const int r0 = tid >> 5;
        const u32 mval = packh(mv[b * 1024 + h * 64 + cp * 2],
                               mv[b * 1024 + h * 64 + cp * 2 + 1]);
        for (int r = r0; r < 128; r += 8) {
            const size_t e = (size_t)(b * LDIM + q0 + r) * 512 + h * 32 + cp;
            ctx[e] = mval;
        }
        return;
    }

    const int lane = tid & 31;
    const int w = tid >> 5;
    const int wm = w * 16;
    const int g = lane >> 2;
    const int qd = lane & 3;

    const size_t hoff = (size_t)bh * LDIM * DDIM;
    const __half* qg = g_q + hoff;
    const __half* kg = g_k + hoff;
    const __half* vg = g_v + hoff;

    {
        const int row = tid >> 1;
        const int c0 = (tid & 1) * 4;
        const size_t src = (size_t)(q0 + row) * DDIM;
#pragma unroll
        for (int c = 0; c < 4; c++)
            cpasync16(sb + Q_OFF + (u32)((row * STR + (c0 + c) * 8) * 2),
                      qg + src + (c0 + c) * 8);
    }
    attn_issue_kv(sb + ST_BASE, 0, tid, kg, vg);
    cp_commit();

    const int qend = min(q0 + 127, sl - 1);
    const int ntiles = (qend >> 6) + 1;

    float o[8][4];
    float mrow[2], lrow[2];
#pragma unroll
    for (int j = 0; j < 8; j++)
#pragma unroll
        for (int c = 0; c < 4; c++) o[j][c] = 0.f;
    mrow[0] = mrow[1] = -1e30f;
    lrow[0] = lrow[1] = 0.f;

    for (int t = 0; t < ntiles; t++) {
        if (t + 1 < ntiles) {
            attn_issue_kv(sb + ST_BASE + (u32)((t + 1) & 1) * ST_SZ, (t + 1) << 6,
                          tid, kg, vg);
            cp_commit();
            cp_wait1();
        } else {
            cp_wait0();
        }
        __syncthreads();

        const u32 kb_ = sb + ST_BASE + (u32)(t & 1) * ST_SZ;

        // ----- S = Q K^T -----
        float s[8][4];
#pragma unroll
        for (int j = 0; j < 8; j++)
#pragma unroll
            for (int c = 0; c < 4; c++) s[j][c] = 0.f;

#pragma unroll
        for (int kf = 0; kf < 4; kf++) {
            u32 aq[4];
            const u32 ad = sb + Q_OFF + (u32)(((wm + (lane & 15)) * STR
                                  + kf * 16 + (lane >> 4) * 8) * 2);
            ldsm4(aq[0], aq[1], aq[2], aq[3], ad);
#pragma unroll
            for (int p = 0; p < 4; p++) {
                const u32 kd = kb_ + K_O + (u32)(((p * 16 + (lane & 15)) * STR
                                      + kf * 16 + (lane >> 4) * 8) * 2);
                u32 t0, t1, t2, t3;
                u32 bk0[2], bk1[2];
                ldsm4(t0, t1, t2, t3, kd);
                bk0[0] = t0; bk0[1] = t2; bk1[0] = t1; bk1[1] = t3;
                mma16816(s[2 * p], aq, bk0);
                mma16816(s[2 * p + 1], aq, bk1);
            }
        }

        // ----- mask (diagonal tiles only) + online softmax in exp2 domain ----
        const int kbase = t << 6;
        const bool interior = (kbase + 63) <= (q0 + wm);   // warp-uniform
#pragma unroll
        for (int hl = 0; hl < 2; hl++) {
            const int qi = q0 + wm + g + hl * 8;
            float mx = -1e30f;
            if (interior) {
#pragma unroll
                for (int nf = 0; nf < 8; nf++)
                    mx = fmaxf(mx, fmaxf(s[nf][hl * 2], s[nf][hl * 2 + 1]));
            } else {
#pragma unroll
                for (int nf = 0; nf < 8; nf++) {
                    const int c0 = kbase + nf * 8 + qd * 2;
                    float s0 = s[nf][hl * 2];
                    float s1 = s[nf][hl * 2 + 1];
                    if (c0 > qi) s0 = -1e30f;
                    if (c0 + 1 > qi) s1 = -1e30f;
                    s[nf][hl * 2] = s0;
                    s[nf][hl * 2 + 1] = s1;
                    mx = fmaxf(mx, fmaxf(s0, s1));
                }
            }
            mx = fmaxf(mx, __shfl_xor_sync(0xffffffffu, mx, 1));
            mx = fmaxf(mx, __shfl_xor_sync(0xffffffffu, mx, 2));
            const float mnew = fmaxf(mrow[hl], mx);
            const float sc = fexp2(mrow[hl] - mnew);
            mrow[hl] = mnew;
            float ps = 0.f;
#pragma unroll
            for (int nf = 0; nf < 8; nf++) {
                float p0 = fexp2(s[nf][hl * 2] - mnew);
                float p1 = fexp2(s[nf][hl * 2 + 1] - mnew);
                s[nf][hl * 2] = p0;
                s[nf][hl * 2 + 1] = p1;
                ps += p0 + p1;
                o[nf][hl * 2] *= sc;
                o[nf][hl * 2 + 1] *= sc;
            }
            ps += __shfl_xor_sync(0xffffffffu, ps, 1);
            ps += __shfl_xor_sync(0xffffffffu, ps, 2);
            lrow[hl] = lrow[hl] * sc + ps;
        }

        // ----- O += P V -----
#pragma unroll
        for (int kg2 = 0; kg2 < 4; kg2++) {
            u32 ap[4];
            ap[0] = packh(s[2 * kg2][0], s[2 * kg2][1]);
            ap[1] = packh(s[2 * kg2][2], s[2 * kg2][3]);
            ap[2] = packh(s[2 * kg2 + 1][0], s[2 * kg2 + 1][1]);
            ap[3] = packh(s[2 * kg2 + 1][2], s[2 * kg2 + 1][3]);
#pragma unroll
            for (int dp = 0; dp < 4; dp++) {
                const u32 vrow = kb_ + V_O
                    + (u32)(((kg2 * 16 + (lane & 7) + ((lane >> 3) & 1) * 8) * STR
                             + dp * 16 + (lane >> 4) * 8) * 2);
                u32 t0, t1, t2, t3;
                u32 bv0[2], bv1[2];
                ldsm4t(t0, t1, t2, t3, vrow);
                bv0[0] = t0; bv0[1] = t1; bv1[0] = t2; bv1[1] = t3;
                mma16816(o[2 * dp], ap, bv0);
                mma16816(o[2 * dp + 1], ap, bv1);
            }
        }
        __syncthreads();
    }

    // ----- epilogue -----
#pragma unroll
    for (int hl = 0; hl < 2; hl++) {
        const int qi = q0 + wm + g + hl * 8;
        const size_t ebase = (size_t)(b * LDIM + qi) * 512 + h * 32;
        if (qi < sl) {
            const float inv = 1.f / lrow[hl];
#pragma unroll
            for (int nf = 0; nf < 8; nf++) {
                const float o0 = o[nf][hl * 2] * inv;
                const float o1 = o[nf][hl * 2 + 1] * inv;
                ctx[ebase + nf * 4 + qd] = packh(o0, o1);
            }
        } else {
#pragma unroll
            for (int nf = 0; nf < 8; nf++) {
                const int col = h * 64 + nf * 8 + qd * 2;
                ctx[ebase + nf * 4 + qd] = packh(mv[b * 1024 + col],
                                                 mv[b * 1024 + col + 1]);
            }
        }
    }
}

// ---------------------------------------------------------------------------
extern "C" void kernel_launch(void* const* d_in, const int* in_sizes, int n_in,
                              void* d_out, int out_size)
{
    const float* hs = (const float*)d_in[0];
    const int* sl   = (const int*)d_in[1];
    const float* Wq = (const float*)d_in[2];
    const float* bq = (const float*)d_in[3];
    const float* Wk = (const float*)d_in[4];
    const float* Wv = (const float*)d_in[5];
    const float* bv = (const float*)d_in[6];
    const float* Wo = (const float*)d_in[7];
    const float* bo = (const float*)d_in[8];
    float* out = (float*)d_out;

    __half *q, *k, *v, *hsx, *ctx, *wx;
    float* mv;
    cudaGetSymbolAddress((void**)&q, g_q);
    cudaGetSymbolAddress((void**)&k, g_k);
    cudaGetSymbolAddress((void**)&v, g_v);
    cudaGetSymbolAddress((void**)&hsx, g_hs);
    cudaGetSymbolAddress((void**)&ctx, g_ctx);
    cudaGetSymbolAddress((void**)&wx, g_w);
    cudaGetSymbolAddress((void**)&mv, g_meanv);

    cudaFuncSetAttribute(gemm_h, cudaFuncAttributeMaxDynamicSharedMemorySize, G_SMEM);
    cudaFuncSetAttribute(attn_mma, cudaFuncAttributeMaxDynamicSharedMemorySize, ATT_SMEM);

    conv_all<<<(HS4 + 4 * W4) / 256, 256>>>(hs, Wq, Wk, Wv, Wo, hsx, wx);

    dim3 g3(EDIM / 256, MDIM / 128, 3);
    gemm_h<<<g3, 512, G_SMEM>>>(hsx, wx, bq, bv, nullptr,
                                (u32*)q, (u32*)k, (u32*)v, 1);

    meanv_kernel<<<BDIM * HDIM, 1024>>>(mv);

    dim3 ga(LDIM / 128, BDIM * HDIM);   // (16, 32)
    attn_mma<<<ga, 256, ATT_SMEM>>>(sl, mv, (u32*)ctx);

    dim3 g1(EDIM / 256, MDIM / 128, 1);
    gemm_h<<<g1, 512, G_SMEM>>>(ctx, wx + 3 * (size_t)WSZ, bo, nullptr, out,
                                nullptr, nullptr, nullptr, 0);
}

// round 15
// speedup vs baseline: 1.0801x; 1.0048x over previous
#include <cuda_runtime.h>
#include <cuda_fp16.h>
#include <cstdint>
#include <math.h>

typedef unsigned int u32;

#define BDIM 2
#define LDIM 2048
#define EDIM 1024
#define HDIM 16
#define DDIM 64
#define MDIM (BDIM * LDIM)   // 4096
#define WSZ (EDIM * EDIM)

// ---------------- scratch (device globals; allocation is forbidden) --------
__device__ __half g_q[BDIM * HDIM * LDIM * DDIM];   // [B,H,L,D]
__device__ __half g_k[BDIM * HDIM * LDIM * DDIM];
__device__ __half g_v[BDIM * HDIM * LDIM * DDIM];
__device__ __half g_hs[MDIM * EDIM];
__device__ __half g_ctx[MDIM * EDIM];               // [B,L,E]
__device__ __half g_w[4 * EDIM * EDIM];             // Wq,Wk,Wv,Wo
__device__ float g_meanv[BDIM * HDIM * DDIM];       // [B,H,D]

// ---------------------------------------------------------------------------
// helpers
// ---------------------------------------------------------------------------
__device__ __forceinline__ u32 packh(float lo, float hi) {
    u32 d;
    asm("cvt.rn.f16x2.f32 %0, %1, %2;" : "=r"(d) : "f"(hi), "f"(lo));
    return d;
}
__device__ __forceinline__ float fexp2(float x) {
    float r;
    asm("ex2.approx.ftz.f32 %0, %1;" : "=f"(r) : "f"(x));
    return r;
}

__device__ __forceinline__ void cpasync16(u32 dst, const void* src) {
    asm volatile("cp.async.cg.shared.global [%0], [%1], 16;\n" :: "r"(dst), "l"(src));
}
__device__ __forceinline__ void cp_commit() { asm volatile("cp.async.commit_group;\n"); }
__device__ __forceinline__ void cp_wait1() { asm volatile("cp.async.wait_group 1;\n"); }
__device__ __forceinline__ void cp_wait0() { asm volatile("cp.async.wait_group 0;\n"); }

__device__ __forceinline__ void ldsm4(u32& r0, u32& r1, u32& r2, u32& r3, u32 addr) {
    asm volatile("ldmatrix.sync.aligned.m8n8.x4.shared.b16 {%0,%1,%2,%3}, [%4];"
        : "=r"(r0), "=r"(r1), "=r"(r2), "=r"(r3) : "r"(addr));
}
__device__ __forceinline__ void ldsm4t(u32& r0, u32& r1, u32& r2, u32& r3, u32 addr) {
    asm volatile("ldmatrix.sync.aligned.m8n8.x4.trans.shared.b16 {%0,%1,%2,%3}, [%4];"
        : "=r"(r0), "=r"(r1), "=r"(r2), "=r"(r3) : "r"(addr));
}
__device__ __forceinline__ void mma16816(float* acc, const u32* a, const u32* b) {
    asm volatile("mma.sync.aligned.m16n8k16.row.col.f32.f16.f16.f32 "
        "{%0,%1,%2,%3}, {%4,%5,%6,%7}, {%8,%9}, {%0,%1,%2,%3};"
        : "+f"(acc[0]), "+f"(acc[1]), "+f"(acc[2]), "+f"(acc[3])
        : "r"(a[0]), "r"(a[1]), "r"(a[2]), "r"(a[3]), "r"(b[0]), "r"(b[1]));
}

// ---------------------------------------------------------------------------
// Fused fp32 -> fp16 convert for hidden_states + all 4 weight matrices
// ---------------------------------------------------------------------------
#define HS4 (MDIM * EDIM / 4)
#define W4 (WSZ / 4)

__global__ __launch_bounds__(256)
void conv_all(const float* __restrict__ hs,
              const float* __restrict__ w0, const float* __restrict__ w1,
              const float* __restrict__ w2, const float* __restrict__ w3,
              __half* __restrict__ ohs, __half* __restrict__ ow)
{
    int i = blockIdx.x * blockDim.x + threadIdx.x;
    const float* src;
    uint2* dst;
    int j;
    if (i < HS4) {
        src = hs; j = i; dst = (uint2*)ohs + i;
    } else {
        const int t = i - HS4;
        const int m = t / W4;
        j = t - m * W4;
        src = (m == 0) ? w0 : (m == 1) ? w1 : (m == 2) ? w2 : w3;
        dst = (uint2*)ow + t;
    }
    float4 v = ((const float4*)src)[j];
    uint2 hv;
    hv.x = packh(v.x, v.y);
    hv.y = packh(v.z, v.w);
    *dst = hv;
}

// ---------------------------------------------------------------------------
// mean(V): single-kernel deterministic reduction. grid=32, block=1024.
// ---------------------------------------------------------------------------
__global__ __launch_bounds__(1024)
void meanv_kernel(float* __restrict__ mv)
{
    __shared__ float red[1024];
    const int bh = blockIdx.x;
    const int tid = threadIdx.x;
    const int d = tid & 63;
    const int sub = tid >> 6;
    const __half* vb = g_v + (size_t)bh * LDIM * DDIM;
    const int l0 = sub * 128;
    float s = 0.f;
#pragma unroll 4
    for (int l = l0; l < l0 + 128; l++)
        s += __half2float(vb[(size_t)l * DDIM + d]);
    red[tid] = s;
    __syncthreads();
    if (tid < 64) {
        float t = 0.f;
#pragma unroll
        for (int k = 0; k < 16; k++)
            t += red[d + 64 * k];
        mv[bh * DDIM + d] = t * (1.0f / 2048.0f);
    }
}

// ---------------------------------------------------------------------------
// fp16 tensor-core NT GEMM, fused-QKV capable (round-10 validated).
// ---------------------------------------------------------------------------
#define SSTR 72
#define A_ARR (128 * SSTR * 2)
#define B_ARR (256 * SSTR * 2)
#define O_A 0
#define O_B A_ARR
#define STG (A_ARR + B_ARR)
#define G_SMEM (3 * STG)

__device__ __forceinline__ void g_issue(
    u32 sbase, int s, int k0, int tid,
    const __half* A, const __half* B, int bm, int bn)
{
    const u32 st = sbase + (u32)(s % 3) * STG;
#pragma unroll
    for (int i = 0; i < 2; i++) {
        const int c = tid + i * 512;
        const int row = c >> 3, ch = c & 7;
        const u32 so = (u32)(row * (SSTR * 2) + ch * 16);
        cpasync16(st + O_A + so, A + (size_t)(bm + row) * EDIM + k0 + ch * 8);
    }
#pragma unroll
    for (int i = 0; i < 4; i++) {
        const int c = tid + i * 512;
        const int row = c >> 3, ch = c & 7;
        const u32 so = (u32)(row * (SSTR * 2) + ch * 16);
        cpasync16(st + O_B + so, B + (size_t)(bn + row) * EDIM + k0 + ch * 8);
    }
    cp_commit();
}

extern "C" __global__ __launch_bounds__(512, 1)
void gemm_h(const __half* __restrict__ Ag, const __half* __restrict__ Wbase,
            const float* __restrict__ b0, const float* __restrict__ b2,
            float* __restrict__ out,
            u32* __restrict__ o0, u32* __restrict__ o1, u32* __restrict__ o2,
            int fused)
{
    extern __shared__ __align__(16) char dynsmem[];
    const u32 sbase = (u32)__cvta_generic_to_shared(dynsmem);
    const int bm = blockIdx.y * 128;
    const int bn = blockIdx.x * 256;
    const int z = blockIdx.z;
    const int tid = threadIdx.x;
    const int lane = tid & 31;
    const int wid = tid >> 5;
    const int wm = (wid & 3) * 32;
    const int wn = (wid >> 2) * 64;

    const __half* Bg = Wbase + (size_t)z * WSZ;
    const float* bias;
    float alpha;
    u32* outq;
    if (fused) {
        bias = (z == 0) ? b0 : ((z == 2) ? b2 : nullptr);
        alpha = (z == 0) ? 0.125f * 1.4426950408889634f : 1.0f;
        outq = (z == 0) ? o0 : ((z == 1) ? o1 : o2);
    } else {
        bias = b0; alpha = 1.0f; outq = nullptr;
    }

    float acc[2][8][4];
#pragma unroll
    for (int i = 0; i < 2; i++)
#pragma unroll
        for (int j = 0; j < 8; j++)
#pragma unroll
            for (int c = 0; c < 4; c++) acc[i][j][c] = 0.f;

    const int lrA = wm + (lane & 15);
    const int lrB = wn + (lane & 15);
    const int lcol = (lane >> 4) * 8;

    const int NIT = EDIM / 64;
    g_issue(sbase, 0, 0, tid, Ag, Bg, bm, bn);
    g_issue(sbase, 1, 64, tid, Ag, Bg, bm, bn);

    for (int it = 0; it < NIT; it++) {
        if (it + 1 < NIT) cp_wait1(); else cp_wait0();
        __syncthreads();
        if (it + 2 < NIT)
            g_issue(sbase, it + 2, (it + 2) * 64, tid, Ag, Bg, bm, bn);

        const u32 st = sbase + (u32)(it % 3) * STG;
#pragma unroll
        for (int ks = 0; ks < 4; ks++) {
            const int kb = ks * 16;
            u32 ah[2][4];
#pragma unroll
            for (int mt = 0; mt < 2; mt++) {
                const u32 ad = st + O_A + (u32)((lrA + mt * 16) * SSTR + kb + lcol) * 2;
                ldsm4(ah[mt][0], ah[mt][1], ah[mt][2], ah[mt][3], ad);
            }
#pragma unroll
            for (int p = 0; p < 4; p++) {
                const u32 bd = st + O_B + (u32)((lrB + p * 16) * SSTR + kb + lcol) * 2;
                u32 t0, t1, t2, t3;
                u32 b0r[2], b1r[2];
                ldsm4(t0, t1, t2, t3, bd);
                b0r[0] = t0; b0r[1] = t2; b1r[0] = t1; b1r[1] = t3;
#pragma unroll
                for (int mt = 0; mt < 2; mt++) {
                    mma16816(acc[mt][2 * p], ah[mt], b0r);
                    mma16816(acc[mt][2 * p + 1], ah[mt], b1r);
                }
            }
        }
        __syncthreads();
    }

#pragma unroll
    for (int mt = 0; mt < 2; mt++) {
#pragma unroll
        for (int nt = 0; nt < 8; nt++) {
#pragma unroll
            for (int r = 0; r < 2; r++) {
                const int row = bm + wm + mt * 16 + (lane >> 2) + r * 8;
                const int col0 = bn + wn + nt * 8 + (lane & 3) * 2;
                float v0 = acc[mt][nt][r * 2 + 0];
                float v1 = acc[mt][nt][r * 2 + 1];
                if (bias) { v0 += bias[col0]; v1 += bias[col0 + 1]; }
                v0 *= alpha; v1 *= alpha;
                const int b = row >> 11;
                const int l = row & (LDIM - 1);
                if (fused) {
                    const int h = col0 >> 6;
                    const int d = col0 & (DDIM - 1);
                    const size_t e = (((size_t)(b * HDIM + h) * LDIM) + l) * DDIM + d;
                    outq[e >> 1] = packh(v0, v1);
                } else {
                    out[(size_t)row * EDIM + col0] = v0;
                    out[(size_t)row * EDIM + col0 + 1] = v1;
                }
            }
        }
    }
}

// ---------------------------------------------------------------------------
// fp16 tensor-core flash attention, 256 threads / 8 warps, warp = 16 rows.
// 3-stage KV ring -> single __syncthreads per tile; per-warp causal skip;
// exp2-domain softmax; invalid rows handled inline.
// ---------------------------------------------------------------------------
#define STR 72
#define Q_OFF 0
#define KT_B (64 * STR * 2)               // 9216
#define ST_BASE (128 * STR * 2)           // 18432
#define ST_SZ (2 * KT_B)                  // 18432 per stage (K+V)
#define K_O 0
#define V_O KT_B
#define ATT_SMEM (ST_BASE + 3 * ST_SZ)    // 73728

__device__ __forceinline__ void attn_issue_kv(u32 base, int kbase, int tid,
                                              const __half* kg, const __half* vg)
{
    const int row = tid >> 2;
    const int c0 = (tid & 3) * 2;
#pragma unroll
    for (int c = 0; c < 2; c++) {
        const int ch = c0 + c;
        const u32 off = (u32)((row * STR + ch * 8) * 2);
        const size_t src = (size_t)(kbase + row) * DDIM + ch * 8;
        cpasync16(base + K_O + off, kg + src);
        cpasync16(base + V_O + off, vg + src);
    }
}

__global__ __launch_bounds__(256)
void attn_mma(const int* __restrict__ seq_len, const float* __restrict__ mv,
              u32* __restrict__ ctx)
{
    extern __shared__ __align__(16) char sm[];
    const u32 sb = (u32)__cvta_generic_to_shared(sm);
    const int bh = blockIdx.y;
    const int b = bh >> 4;
    const int h = bh & (HDIM - 1);
    const int qt = (int)gridDim.x - 1 - (int)blockIdx.x;
    const int q0 = qt * 128;
    const int sl = seq_len[b];
    const int tid = threadIdx.x;

    if (q0 >= sl) {
        const int cp = tid & 31;
        const int r0 = tid >> 5;
        const u32 mval = packh(mv[b * 1024 + h * 64 + cp * 2],
                               mv[b * 1024 + h * 64 + cp * 2 + 1]);
        for (int r = r0; r < 128; r += 8) {
            const size_t e = (size_t)(b * LDIM + q0 + r) * 512 + h * 32 + cp;
            ctx[e] = mval;
        }
        return;
    }

    const int lane = tid & 31;
    const int w = tid >> 5;
    const int wm = w * 16;
    const int g = lane >> 2;
    const int qd = lane & 3;

    const size_t hoff = (size_t)bh * LDIM * DDIM;
    const __half* qg = g_q + hoff;
    const __half* kg = g_k + hoff;
    const __half* vg = g_v + hoff;

    const int qend = min(q0 + 127, sl - 1);
    const int ntiles = (qend >> 6) + 1;

    // prologue: group1 = Q + KV0, group2 = KV1
    {
        const int row = tid >> 1;
        const int c0 = (tid & 1) * 4;
        const size_t src = (size_t)(q0 + row) * DDIM;
#pragma unroll
        for (int c = 0; c < 4; c++)
            cpasync16(sb + Q_OFF + (u32)((row * STR + (c0 + c) * 8) * 2),
                      qg + src + (c0 + c) * 8);
    }
    attn_issue_kv(sb + ST_BASE, 0, tid, kg, vg);
    cp_commit();
    if (ntiles > 1) {
        attn_issue_kv(sb + ST_BASE + ST_SZ, 64, tid, kg, vg);
        cp_commit();
    }

    float o[8][4];
    float mrow[2], lrow[2];
#pragma unroll
    for (int j = 0; j < 8; j++)
#pragma unroll
        for (int c = 0; c < 4; c++) o[j][c] = 0.f;
    mrow[0] = mrow[1] = -1e30f;
    lrow[0] = lrow[1] = 0.f;

    const int myend = q0 + wm + 15;       // last key this warp ever needs

    for (int t = 0; t < ntiles; t++) {
        if (t + 1 < ntiles) cp_wait1(); else cp_wait0();
        __syncthreads();                  // single barrier: tile t ready,
                                          // buffer (t+2)%3 free (consumed at t-1)
        if (t + 2 < ntiles) {
            attn_issue_kv(sb + ST_BASE + (u32)((t + 2) % 3) * ST_SZ,
                          (t + 2) << 6, tid, kg, vg);
            cp_commit();
        }

        const int kbase = t << 6;
        if (kbase > myend) continue;      // warp-uniform: tile fully masked

        const u32 kb_ = sb + ST_BASE + (u32)(t % 3) * ST_SZ;

        // ----- S = Q K^T -----
        float s[8][4];
#pragma unroll
        for (int j = 0; j < 8; j++)
#pragma unroll
            for (int c = 0; c < 4; c++) s[j][c] = 0.f;

#pragma unroll
        for (int kf = 0; kf < 4; kf++) {
            u32 aq[4];
            const u32 ad = sb + Q_OFF + (u32)(((wm + (lane & 15)) * STR
                                  + kf * 16 + (lane >> 4) * 8) * 2);
            ldsm4(aq[0], aq[1], aq[2], aq[3], ad);
#pragma unroll
            for (int p = 0; p < 4; p++) {
                const u32 kd = kb_ + K_O + (u32)(((p * 16 + (lane & 15)) * STR
                                      + kf * 16 + (lane >> 4) * 8) * 2);
                u32 t0, t1, t2, t3;
                u32 bk0[2], bk1[2];
                ldsm4(t0, t1, t2, t3, kd);
                bk0[0] = t0; bk0[1] = t2; bk1[0] = t1; bk1[1] = t3;
                mma16816(s[2 * p], aq, bk0);
                mma16816(s[2 * p + 1], aq, bk1);
            }
        }

        // ----- mask (diagonal only) + online softmax (exp2 domain) -----
        const bool interior = (kbase + 63) <= (q0 + wm);
#pragma unroll
        for (int hl = 0; hl < 2; hl++) {
            const int qi = q0 + wm + g + hl * 8;
            float mx = -1e30f;
            if (interior) {
#pragma unroll
                for (int nf = 0; nf < 8; nf++)
                    mx = fmaxf(mx, fmaxf(s[nf][hl * 2], s[nf][hl * 2 + 1]));
            } else {
#pragma unroll
                for (int nf = 0; nf < 8; nf++) {
                    const int c0 = kbase + nf * 8 + qd * 2;
                    float s0 = s[nf][hl * 2];
                    float s1 = s[nf][hl * 2 + 1];
                    if (c0 > qi) s0 = -1e30f;
                    if (c0 + 1 > qi) s1 = -1e30f;
                    s[nf][hl * 2] = s0;
                    s[nf][hl * 2 + 1] = s1;
                    mx = fmaxf(mx, fmaxf(s0, s1));
                }
            }
            mx = fmaxf(mx, __shfl_xor_sync(0xffffffffu, mx, 1));
            mx = fmaxf(mx, __shfl_xor_sync(0xffffffffu, mx, 2));
            const float mnew = fmaxf(mrow[hl], mx);
            const float sc = fexp2(mrow[hl] - mnew);
            mrow[hl] = mnew;
            float ps = 0.f;
#pragma unroll
            for (int nf = 0; nf < 8; nf++) {
                float p0 = fexp2(s[nf][hl * 2] - mnew);
                float p1 = fexp2(s[nf][hl * 2 + 1] - mnew);
                s[nf][hl * 2] = p0;
                s[nf][hl * 2 + 1] = p1;
                ps += p0 + p1;
                o[nf][hl * 2] *= sc;
                o[nf][hl * 2 + 1] *= sc;
            }
            ps += __shfl_xor_sync(0xffffffffu, ps, 1);
            ps += __shfl_xor_sync(0xffffffffu, ps, 2);
            lrow[hl] = lrow[hl] * sc + ps;
        }

        // ----- O += P V -----
#pragma unroll
        for (int kg2 = 0; kg2 < 4; kg2++) {
            u32 ap[4];
            ap[0] = packh(s[2 * kg2][0], s[2 * kg2][1]);
            ap[1] = packh(s[2 * kg2][2], s[2 * kg2][3]);
            ap[2] = packh(s[2 * kg2 + 1][0], s[2 * kg2 + 1][1]);
            ap[3] = packh(s[2 * kg2 + 1][2], s[2 * kg2 + 1][3]);
#pragma unroll
            for (int dp = 0; dp < 4; dp++) {
                const u32 vrow = kb_ + V_O
                    + (u32)(((kg2 * 16 + (lane & 7) + ((lane >> 3) & 1) * 8) * STR
                             + dp * 16 + (lane >> 4) * 8) * 2);
                u32 t0, t1, t2, t3;
                u32 bv0[2], bv1[2];
                ldsm4t(t0, t1, t2, t3, vrow);
                bv0[0] = t0; bv0[1] = t1; bv1[0] = t2; bv1[1] = t3;
                mma16816(o[2 * dp], ap, bv0);
                mma16816(o[2 * dp + 1], ap, bv1);
            }
        }
    }

    // ----- epilogue -----
#pragma unroll
    for (int hl = 0; hl < 2; hl++) {
        const int qi = q0 + wm + g + hl * 8;
        const size_t ebase = (size_t)(b * LDIM + qi) * 512 + h * 32;
        if (qi < sl) {
            const float inv = 1.f / lrow[hl];
#pragma unroll
            for (int nf = 0; nf < 8; nf++) {
                const float o0 = o[nf][hl * 2] * inv;
                const float o1 = o[nf][hl * 2 + 1] * inv;
                ctx[ebase + nf * 4 + qd] = packh(o0, o1);
            }
        } else {
#pragma unroll
            for (int nf = 0; nf < 8; nf++) {
                const int col = h * 64 + nf * 8 + qd * 2;
                ctx[ebase + nf * 4 + qd] = packh(mv[b * 1024 + col],
                                                 mv[b * 1024 + col + 1]);
            }
        }
    }
}

// ---------------------------------------------------------------------------
extern "C" void kernel_launch(void* const* d_in, const int* in_sizes, int n_in,
                              void* d_out, int out_size)
{
    const float* hs = (const float*)d_in[0];
    const int* sl   = (const int*)d_in[1];
    const float* Wq = (const float*)d_in[2];
    const float* bq = (const float*)d_in[3];
    const float* Wk = (const float*)d_in[4];
    const float* Wv = (const float*)d_in[5];
    const float* bv = (const float*)d_in[6];
    const float* Wo = (const float*)d_in[7];
    const float* bo = (const float*)d_in[8];
    float* out = (float*)d_out;

    __half *q, *k, *v, *hsx, *ctx, *wx;
    float* mv;
    cudaGetSymbolAddress((void**)&q, g_q);
    cudaGetSymbolAddress((void**)&k, g_k);
    cudaGetSymbolAddress((void**)&v, g_v);
    cudaGetSymbolAddress((void**)&hsx, g_hs);
    cudaGetSymbolAddress((void**)&ctx, g_ctx);
    cudaGetSymbolAddress((void**)&wx, g_w);
    cudaGetSymbolAddress((void**)&mv, g_meanv);

    cudaFuncSetAttribute(gemm_h, cudaFuncAttributeMaxDynamicSharedMemorySize, G_SMEM);
    cudaFuncSetAttribute(attn_mma, cudaFuncAttributeMaxDynamicSharedMemorySize, ATT_SMEM);

    conv_all<<<(HS4 + 4 * W4) / 256, 256>>>(hs, Wq, Wk, Wv, Wo, hsx, wx);

    dim3 g3(EDIM / 256, MDIM / 128, 3);
    gemm_h<<<g3, 512, G_SMEM>>>(hsx, wx, bq, bv, nullptr,
                                (u32*)q, (u32*)k, (u32*)v, 1);

    meanv_kernel<<<BDIM * HDIM, 1024>>>(mv);

    dim3 ga(LDIM / 128, BDIM * HDIM);   // (16, 32)
    attn_mma<<<ga, 256, ATT_SMEM>>>(sl, mv, (u32*)ctx);

    dim3 g1(EDIM / 256, MDIM / 128, 1);
    gemm_h<<<g1, 512, G_SMEM>>>(ctx, wx + 3 * (size_t)WSZ, bo, nullptr, out,
                                nullptr, nullptr, nullptr, 0);
}

// round 17
// speedup vs baseline: 1.2638x; 1.1701x over previous
#include <cuda_runtime.h>
#include <cuda_fp16.h>
#include <cstdint>
#include <math.h>

typedef unsigned int u32;

#define BDIM 2
#define LDIM 2048
#define EDIM 1024
#define HDIM 16
#define DDIM 64
#define MDIM (BDIM * LDIM)   // 4096
#define WSZ (EDIM * EDIM)

// ---------------- scratch (device globals; allocation is forbidden) --------
__device__ __half g_q[BDIM * HDIM * LDIM * DDIM];   // [B,H,L,D]
__device__ __half g_k[BDIM * HDIM * LDIM * DDIM];
__device__ __half g_v[BDIM * HDIM * LDIM * DDIM];
__device__ __half g_hs[MDIM * EDIM];
__device__ __half g_ctx[MDIM * EDIM];               // [B,L,E]
__device__ __half g_w[4 * EDIM * EDIM];             // Wq,Wk,Wv,Wo
__device__ float g_meanv[BDIM * HDIM * DDIM];       // [B,H,D]

// ---------------------------------------------------------------------------
// helpers
// ---------------------------------------------------------------------------
__device__ __forceinline__ u32 packh(float lo, float hi) {
    u32 d;
    asm("cvt.rn.f16x2.f32 %0, %1, %2;" : "=r"(d) : "f"(hi), "f"(lo));
    return d;
}
__device__ __forceinline__ float fexp2(float x) {
    float r;
    asm("ex2.approx.ftz.f32 %0, %1;" : "=f"(r) : "f"(x));
    return r;
}

__device__ __forceinline__ void cpasync16(u32 dst, const void* src) {
    asm volatile("cp.async.cg.shared.global [%0], [%1], 16;\n" :: "r"(dst), "l"(src));
}
__device__ __forceinline__ void cp_commit() { asm volatile("cp.async.commit_group;\n"); }
__device__ __forceinline__ void cp_wait1() { asm volatile("cp.async.wait_group 1;\n"); }
__device__ __forceinline__ void cp_wait0() { asm volatile("cp.async.wait_group 0;\n"); }

__device__ __forceinline__ void ldsm4(u32& r0, u32& r1, u32& r2, u32& r3, u32 addr) {
    asm volatile("ldmatrix.sync.aligned.m8n8.x4.shared.b16 {%0,%1,%2,%3}, [%4];"
        : "=r"(r0), "=r"(r1), "=r"(r2), "=r"(r3) : "r"(addr));
}
__device__ __forceinline__ void ldsm4t(u32& r0, u32& r1, u32& r2, u32& r3, u32 addr) {
    asm volatile("ldmatrix.sync.aligned.m8n8.x4.trans.shared.b16 {%0,%1,%2,%3}, [%4];"
        : "=r"(r0), "=r"(r1), "=r"(r2), "=r"(r3) : "r"(addr));
}
__device__ __forceinline__ void mma16816(float* acc, const u32* a, const u32* b) {
    asm volatile("mma.sync.aligned.m16n8k16.row.col.f32.f16.f16.f32 "
        "{%0,%1,%2,%3}, {%4,%5,%6,%7}, {%8,%9}, {%0,%1,%2,%3};"
        : "+f"(acc[0]), "+f"(acc[1]), "+f"(acc[2]), "+f"(acc[3])
        : "r"(a[0]), "r"(a[1]), "r"(a[2]), "r"(a[3]), "r"(b[0]), "r"(b[1]));
}

// ---------------------------------------------------------------------------
// Fused fp32 -> fp16 convert for hidden_states + all 4 weight matrices
// ---------------------------------------------------------------------------
#define HS4 (MDIM * EDIM / 4)
#define W4 (WSZ / 4)

__global__ __launch_bounds__(256)
void conv_all(const float* __restrict__ hs,
              const float* __restrict__ w0, const float* __restrict__ w1,
              const float* __restrict__ w2, const float* __restrict__ w3,
              __half* __restrict__ ohs, __half* __restrict__ ow)
{
    int i = blockIdx.x * blockDim.x + threadIdx.x;
    const float* src;
    uint2* dst;
    int j;
    if (i < HS4) {
        src = hs; j = i; dst = (uint2*)ohs + i;
    } else {
        const int t = i - HS4;
        const int m = t / W4;
        j = t - m * W4;
        src = (m == 0) ? w0 : (m == 1) ? w1 : (m == 2) ? w2 : w3;
        dst = (uint2*)ow + t;
    }
    float4 v = ((const float4*)src)[j];
    uint2 hv;
    hv.x = packh(v.x, v.y);
    hv.y = packh(v.z, v.w);
    *dst = hv;
}

// ---------------------------------------------------------------------------
// mean(V): single-kernel deterministic reduction. grid=32, block=1024.
// ---------------------------------------------------------------------------
__global__ __launch_bounds__(1024)
void meanv_kernel(float* __restrict__ mv)
{
    __shared__ float red[1024];
    const int bh = blockIdx.x;
    const int tid = threadIdx.x;
    const int d = tid & 63;
    const int sub = tid >> 6;
    const __half* vb = g_v + (size_t)bh * LDIM * DDIM;
    const int l0 = sub * 128;
    float s = 0.f;
#pragma unroll 4
    for (int l = l0; l < l0 + 128; l++)
        s += __half2float(vb[(size_t)l * DDIM + d]);
    red[tid] = s;
    __syncthreads();
    if (tid < 64) {
        float t = 0.f;
#pragma unroll
        for (int k = 0; k < 16; k++)
            t += red[d + 64 * k];
        mv[bh * DDIM + d] = t * (1.0f / 2048.0f);
    }
}

// ---------------------------------------------------------------------------
// fp16 tensor-core NT GEMM, fused-QKV capable. Q/K tiles whose within-batch
// row range lies fully beyond seq_len[b] exit immediately (never read).
// ---------------------------------------------------------------------------
#define SSTR 72
#define A_ARR (128 * SSTR * 2)
#define B_ARR (256 * SSTR * 2)
#define O_A 0
#define O_B A_ARR
#define STG (A_ARR + B_ARR)
#define G_SMEM (3 * STG)

__device__ __forceinline__ void g_issue(
    u32 sbase, int s, int k0, int tid,
    const __half* A, const __half* B, int bm, int bn)
{
    const u32 st = sbase + (u32)(s % 3) * STG;
#pragma unroll
    for (int i = 0; i < 2; i++) {
        const int c = tid + i * 512;
        const int row = c >> 3, ch = c & 7;
        const u32 so = (u32)(row * (SSTR * 2) + ch * 16);
        cpasync16(st + O_A + so, A + (size_t)(bm + row) * EDIM + k0 + ch * 8);
    }
#pragma unroll
    for (int i = 0; i < 4; i++) {
        const int c = tid + i * 512;
        const int row = c >> 3, ch = c & 7;
        const u32 so = (u32)(row * (SSTR * 2) + ch * 16);
        cpasync16(st + O_B + so, B + (size_t)(bn + row) * EDIM + k0 + ch * 8);
    }
    cp_commit();
}

extern "C" __global__ __launch_bounds__(512, 1)
void gemm_h(const __half* __restrict__ Ag, const __half* __restrict__ Wbase,
            const float* __restrict__ b0, const float* __restrict__ b2,
            const int* __restrict__ seq_len,
            float* __restrict__ out,
            u32* __restrict__ o0, u32* __restrict__ o1, u32* __restrict__ o2,
            int fused)
{
    extern __shared__ __align__(16) char dynsmem[];
    const u32 sbase = (u32)__cvta_generic_to_shared(dynsmem);
    const int bm = blockIdx.y * 128;
    const int bn = blockIdx.x * 256;
    const int z = blockIdx.z;
    const int tid = threadIdx.x;
    const int lane = tid & 31;
    const int wid = tid >> 5;
    const int wm = (wid & 3) * 32;
    const int wn = (wid >> 2) * 64;

    const __half* Bg = Wbase + (size_t)z * WSZ;
    const float* bias;
    float alpha;
    u32* outq;
    if (fused) {
        // Q/K rows with (l >= seq_len[b]) are never read by attention:
        // skip tiles fully beyond seq_len (WITHIN-BATCH position!).
        if (z <= 1 && (bm & (LDIM - 1)) >= seq_len[bm >> 11]) return;
        bias = (z == 0) ? b0 : ((z == 2) ? b2 : nullptr);
        alpha = (z == 0) ? 0.125f * 1.4426950408889634f : 1.0f;
        outq = (z == 0) ? o0 : ((z == 1) ? o1 : o2);
    } else {
        bias = b0; alpha = 1.0f; outq = nullptr;
    }

    float acc[2][8][4];
#pragma unroll
    for (int i = 0; i < 2; i++)
#pragma unroll
        for (int j = 0; j < 8; j++)
#pragma unroll
            for (int c = 0; c < 4; c++) acc[i][j][c] = 0.f;

    const int lrA = wm + (lane & 15);
    const int lrB = wn + (lane & 15);
    const int lcol = (lane >> 4) * 8;

    const int NIT = EDIM / 64;
    g_issue(sbase, 0, 0, tid, Ag, Bg, bm, bn);
    g_issue(sbase, 1, 64, tid, Ag, Bg, bm, bn);

    for (int it = 0; it < NIT; it++) {
        if (it + 1 < NIT) cp_wait1(); else cp_wait0();
        __syncthreads();
        if (it + 2 < NIT)
            g_issue(sbase, it + 2, (it + 2) * 64, tid, Ag, Bg, bm, bn);

        const u32 st = sbase + (u32)(it % 3) * STG;
#pragma unroll
        for (int ks = 0; ks < 4; ks++) {
            const int kb = ks * 16;
            u32 ah[2][4];
#pragma unroll
            for (int mt = 0; mt < 2; mt++) {
                const u32 ad = st + O_A + (u32)((lrA + mt * 16) * SSTR + kb + lcol) * 2;
                ldsm4(ah[mt][0], ah[mt][1], ah[mt][2], ah[mt][3], ad);
            }
#pragma unroll
            for (int p = 0; p < 4; p++) {
                const u32 bd = st + O_B + (u32)((lrB + p * 16) * SSTR + kb + lcol) * 2;
                u32 t0, t1, t2, t3;
                u32 b0r[2], b1r[2];
                ldsm4(t0, t1, t2, t3, bd);
                b0r[0] = t0; b0r[1] = t2; b1r[0] = t1; b1r[1] = t3;
#pragma unroll
                for (int mt = 0; mt < 2; mt++) {
                    mma16816(acc[mt][2 * p], ah[mt], b0r);
                    mma16816(acc[mt][2 * p + 1], ah[mt], b1r);
                }
            }
        }
        __syncthreads();
    }

#pragma unroll
    for (int mt = 0; mt < 2; mt++) {
#pragma unroll
        for (int nt = 0; nt < 8; nt++) {
#pragma unroll
            for (int r = 0; r < 2; r++) {
                const int row = bm + wm + mt * 16 + (lane >> 2) + r * 8;
                const int col0 = bn + wn + nt * 8 + (lane & 3) * 2;
                float v0 = acc[mt][nt][r * 2 + 0];
                float v1 = acc[mt][nt][r * 2 + 1];
                if (bias) { v0 += bias[col0]; v1 += bias[col0 + 1]; }
                v0 *= alpha; v1 *= alpha;
                const int b = row >> 11;
                const int l = row & (LDIM - 1);
                if (fused) {
                    const int h = col0 >> 6;
                    const int d = col0 & (DDIM - 1);
                    const size_t e = (((size_t)(b * HDIM + h) * LDIM) + l) * DDIM + d;
                    outq[e >> 1] = packh(v0, v1);
                } else {
                    out[(size_t)row * EDIM + col0] = v0;
                    out[(size_t)row * EDIM + col0 + 1] = v1;
                }
            }
        }
    }
}

// ---------------------------------------------------------------------------
// fp16 tensor-core flash attention (round-15 validated): 256 thr / 8 warps,
// 3-stage KV ring, single barrier per tile, per-warp causal skip, exp2
// softmax, invalid rows inline.
// ---------------------------------------------------------------------------
#define STR 72
#define Q_OFF 0
#define KT_B (64 * STR * 2)               // 9216
#define ST_BASE (128 * STR * 2)           // 18432
#define ST_SZ (2 * KT_B)                  // 18432 per stage (K+V)
#define K_O 0
#define V_O KT_B
#define ATT_SMEM (ST_BASE + 3 * ST_SZ)    // 73728

__device__ __forceinline__ void attn_issue_kv(u32 base, int kbase, int tid,
                                              const __half* kg, const __half* vg)
{
    const int row = tid >> 2;
    const int c0 = (tid & 3) * 2;
#pragma unroll
    for (int c = 0; c < 2; c++) {
        const int ch = c0 + c;
        const u32 off = (u32)((row * STR + ch * 8) * 2);
        const size_t src = (size_t)(kbase + row) * DDIM + ch * 8;
        cpasync16(base + K_O + off, kg + src);
        cpasync16(base + V_O + off, vg + src);
    }
}

__global__ __launch_bounds__(256)
void attn_mma(const int* __restrict__ seq_len, const float* __restrict__ mv,
              u32* __restrict__ ctx)
{
    extern __shared__ __align__(16) char sm[];
    const u32 sb = (u32)__cvta_generic_to_shared(sm);
    const int bh = blockIdx.y;
    const int b = bh >> 4;
    const int h = bh & (HDIM - 1);
    const int qt = (int)gridDim.x - 1 - (int)blockIdx.x;
    const int q0 = qt * 128;
    const int sl = seq_len[b];
    const int tid = threadIdx.x;

    if (q0 >= sl) {
        const int cp = tid & 31;
        const int r0 = tid >> 5;
        const u32 mval = packh(mv[b * 1024 + h * 64 + cp * 2],
                               mv[b * 1024 + h * 64 + cp * 2 + 1]);
        for (int r = r0; r < 128; r += 8) {
            const size_t e = (size_t)(b * LDIM + q0 + r) * 512 + h * 32 + cp;
            ctx[e] = mval;
        }
        return;
    }

    const int lane = tid & 31;
    const int w = tid >> 5;
    const int wm = w * 16;
    const int g = lane >> 2;
    const int qd = lane & 3;

    const size_t hoff = (size_t)bh * LDIM * DDIM;
    const __half* qg = g_q + hoff;
    const __half* kg = g_k + hoff;
    const __half* vg = g_v + hoff;

    const int qend = min(q0 + 127, sl - 1);
    const int ntiles = (qend >> 6) + 1;

    {
        const int row = tid >> 1;
        const int c0 = (tid & 1) * 4;
        const size_t src = (size_t)(q0 + row) * DDIM;
#pragma unroll
        for (int c = 0; c < 4; c++)
            cpasync16(sb + Q_OFF + (u32)((row * STR + (c0 + c) * 8) * 2),
                      qg + src + (c0 + c) * 8);
    }
    attn_issue_kv(sb + ST_BASE, 0, tid, kg, vg);
    cp_commit();
    if (ntiles > 1) {
        attn_issue_kv(sb + ST_BASE + ST_SZ, 64, tid, kg, vg);
        cp_commit();
    }

    float o[8][4];
    float mrow[2], lrow[2];
#pragma unroll
    for (int j = 0; j < 8; j++)
#pragma unroll
        for (int c = 0; c < 4; c++) o[j][c] = 0.f;
    mrow[0] = mrow[1] = -1e30f;
    lrow[0] = lrow[1] = 0.f;

    const int myend = q0 + wm + 15;

    for (int t = 0; t < ntiles; t++) {
        if (t + 1 < ntiles) cp_wait1(); else cp_wait0();
        __syncthreads();
        if (t + 2 < ntiles) {
            attn_issue_kv(sb + ST_BASE + (u32)((t + 2) % 3) * ST_SZ,
                          (t + 2) << 6, tid, kg, vg);
            cp_commit();
        }

        const int kbase = t << 6;
        if (kbase > myend) continue;

        const u32 kb_ = sb + ST_BASE + (u32)(t % 3) * ST_SZ;

        float s[8][4];
#pragma unroll
        for (int j = 0; j < 8; j++)
#pragma unroll
            for (int c = 0; c < 4; c++) s[j][c] = 0.f;

#pragma unroll
        for (int kf = 0; kf < 4; kf++) {
            u32 aq[4];
            const u32 ad = sb + Q_OFF + (u32)(((wm + (lane & 15)) * STR
                                  + kf * 16 + (lane >> 4) * 8) * 2);
            ldsm4(aq[0], aq[1], aq[2], aq[3], ad);
#pragma unroll
            for (int p = 0; p < 4; p++) {
                const u32 kd = kb_ + K_O + (u32)(((p * 16 + (lane & 15)) * STR
                                      + kf * 16 + (lane >> 4) * 8) * 2);
                u32 t0, t1, t2, t3;
                u32 bk0[2], bk1[2];
                ldsm4(t0, t1, t2, t3, kd);
                bk0[0] = t0; bk0[1] = t2; bk1[0] = t1; bk1[1] = t3;
                mma16816(s[2 * p], aq, bk0);
                mma16816(s[2 * p + 1], aq, bk1);
            }
        }

        const bool interior = (kbase + 63) <= (q0 + wm);
#pragma unroll
        for (int hl = 0; hl < 2; hl++) {
            const int qi = q0 + wm + g + hl * 8;
            float mx = -1e30f;
            if (interior) {
#pragma unroll
                for (int nf = 0; nf < 8; nf++)
                    mx = fmaxf(mx, fmaxf(s[nf][hl * 2], s[nf][hl * 2 + 1]));
            } else {
#pragma unroll
                for (int nf = 0; nf < 8; nf++) {
                    const int c0 = kbase + nf * 8 + qd * 2;
                    float s0 = s[nf][hl * 2];
                    float s1 = s[nf][hl * 2 + 1];
                    if (c0 > qi) s0 = -1e30f;
                    if (c0 + 1 > qi) s1 = -1e30f;
                    s[nf][hl * 2] = s0;
                    s[nf][hl * 2 + 1] = s1;
                    mx = fmaxf(mx, fmaxf(s0, s1));
                }
            }
            mx = fmaxf(mx, __shfl_xor_sync(0xffffffffu, mx, 1));
            mx = fmaxf(mx, __shfl_xor_sync(0xffffffffu, mx, 2));
            const float mnew = fmaxf(mrow[hl], mx);
            const float sc = fexp2(mrow[hl] - mnew);
            mrow[hl] = mnew;
            float ps = 0.f;
#pragma unroll
            for (int nf = 0; nf < 8; nf++) {
                float p0 = fexp2(s[nf][hl * 2] - mnew);
                float p1 = fexp2(s[nf][hl * 2 + 1] - mnew);
                s[nf][hl * 2] = p0;
                s[nf][hl * 2 + 1] = p1;
                ps += p0 + p1;
                o[nf][hl * 2] *= sc;
                o[nf][hl * 2 + 1] *= sc;
            }
            ps += __shfl_xor_sync(0xffffffffu, ps, 1);
            ps += __shfl_xor_sync(0xffffffffu, ps, 2);
            lrow[hl] = lrow[hl] * sc + ps;
        }

#pragma unroll
        for (int kg2 = 0; kg2 < 4; kg2++) {
            u32 ap[4];
            ap[0] = packh(s[2 * kg2][0], s[2 * kg2][1]);
            ap[1] = packh(s[2 * kg2][2], s[2 * kg2][3]);
            ap[2] = packh(s[2 * kg2 + 1][0], s[2 * kg2 + 1][1]);
            ap[3] = packh(s[2 * kg2 + 1][2], s[2 * kg2 + 1][3]);
#pragma unroll
            for (int dp = 0; dp < 4; dp++) {
                const u32 vrow = kb_ + V_O
                    + (u32)(((kg2 * 16 + (lane & 7) + ((lane >> 3) & 1) * 8) * STR
                             + dp * 16 + (lane >> 4) * 8) * 2);
                u32 t0, t1, t2, t3;
                u32 bv0[2], bv1[2];
                ldsm4t(t0, t1, t2, t3, vrow);
                bv0[0] = t0; bv0[1] = t1; bv1[0] = t2; bv1[1] = t3;
                mma16816(o[2 * dp], ap, bv0);
                mma16816(o[2 * dp + 1], ap, bv1);
            }
        }
    }

#pragma unroll
    for (int hl = 0; hl < 2; hl++) {
        const int qi = q0 + wm + g + hl * 8;
        const size_t ebase = (size_t)(b * LDIM + qi) * 512 + h * 32;
        if (qi < sl) {
            const float inv = 1.f / lrow[hl];
#pragma unroll
            for (int nf = 0; nf < 8; nf++) {
                const float o0 = o[nf][hl * 2] * inv;
                const float o1 = o[nf][hl * 2 + 1] * inv;
                ctx[ebase + nf * 4 + qd] = packh(o0, o1);
            }
        } else {
#pragma unroll
            for (int nf = 0; nf < 8; nf++) {
                const int col = h * 64 + nf * 8 + qd * 2;
                ctx[ebase + nf * 4 + qd] = packh(mv[b * 1024 + col],
                                                 mv[b * 1024 + col + 1]);
            }
        }
    }
}

// ---------------------------------------------------------------------------
extern "C" void kernel_launch(void* const* d_in, const int* in_sizes, int n_in,
                              void* d_out, int out_size)
{
    const float* hs = (const float*)d_in[0];
    const int* sl   = (const int*)d_in[1];
    const float* Wq = (const float*)d_in[2];
    const float* bq = (const float*)d_in[3];
    const float* Wk = (const float*)d_in[4];
    const float* Wv = (const float*)d_in[5];
    const float* bv = (const float*)d_in[6];
    const float* Wo = (const float*)d_in[7];
    const float* bo = (const float*)d_in[8];
    float* out = (float*)d_out;

    __half *q, *k, *v, *hsx, *ctx, *wx;
    float* mv;
    cudaGetSymbolAddress((void**)&q, g_q);
    cudaGetSymbolAddress((void**)&k, g_k);
    cudaGetSymbolAddress((void**)&v, g_v);
    cudaGetSymbolAddress((void**)&hsx, g_hs);
    cudaGetSymbolAddress((void**)&ctx, g_ctx);
    cudaGetSymbolAddress((void**)&wx, g_w);
    cudaGetSymbolAddress((void**)&mv, g_meanv);

    cudaFuncSetAttribute(gemm_h, cudaFuncAttributeMaxDynamicSharedMemorySize, G_SMEM);
    cudaFuncSetAttribute(attn_mma, cudaFuncAttributeMaxDynamicSharedMemorySize, ATT_SMEM);

    conv_all<<<(HS4 + 4 * W4) / 256, 256>>>(hs, Wq, Wk, Wv, Wo, hsx, wx);

    dim3 g3(EDIM / 256, MDIM / 128, 3);
    gemm_h<<<g3, 512, G_SMEM>>>(hsx, wx, bq, bv, sl, nullptr,
                                (u32*)q, (u32*)k, (u32*)v, 1);

    meanv_kernel<<<BDIM * HDIM, 1024>>>(mv);

    dim3 ga(LDIM / 128, BDIM * HDIM);   // (16, 32)
    attn_mma<<<ga, 256, ATT_SMEM>>>(sl, mv, (u32*)ctx);

    dim3 g1(EDIM / 256, MDIM / 128, 1);
    gemm_h<<<g1, 512, G_SMEM>>>(ctx, wx + 3 * (size_t)WSZ, bo, nullptr, sl, out,
                                nullptr, nullptr, nullptr, 0);
}